// round 4
// baseline (speedup 1.0000x reference)
#include <cuda_runtime.h>
#include <cuda_bf16.h>
#include <cstdint>
#include <math.h>

// Problem constants
constexpr int BS = 16, C = 64, H = 128, W = 128;
constexpr int HW = H * W;           // 16384
constexpr int NC = 80;
constexpr int TOPK = 128;
constexpr int NKEY = TOPK + NC;     // 208

// Scratch (device globals; no allocation allowed)
__device__ int   g_peak[BS * NC];
__device__ float g_cmask[BS * NC];
__device__ float g_hmfree[BS * HW];
__device__ float g_maxval[BS * HW];
__device__ int   g_argcls[BS * HW];
__device__ int   g_topk_idx[BS * TOPK];
__device__ float g_topk_val[BS * TOPK];
__device__ int   g_topk_cls[BS * TOPK];
__device__ float g_q[BS * NC * C];
__device__ float g_ktop[BS * TOPK * C];
__device__ float g_contrib[BS * NC];

// ---------------------------------------------------------------------------
__global__ void init_kernel() {
    int t = blockIdx.x * blockDim.x + threadIdx.x;
    if (t < BS * NC) { g_peak[t] = -1; g_cmask[t] = 0.f; }
}

// ---------------------------------------------------------------------------
// Scan hm: peaks, class_mask, hm_free. A PAIR of threads covers one float4
// pixel group: half 0 -> classes 0..39, half 1 -> classes 40..79. Combine
// the free-flag via shfl_xor(1). Doubles in-flight loads vs one-thread-per-pix.
__global__ void hm_kernel(const float* __restrict__ hm) {
    int t    = blockIdx.x * blockDim.x + threadIdx.x;
    int half = t & 1;
    int pair = t >> 1;
    int b    = pair >> 12;
    int p4   = (pair & 4095) << 2;
    int cb   = half * 40;
    const float* base = hm + (size_t)b * NC * HW + (size_t)cb * HW + p4;
    float f0 = 1.f, f1 = 1.f, f2 = 1.f, f3 = 1.f;
#pragma unroll 1
    for (int cc = 0; cc < 40; cc += 8) {
        float4 r[8];
#pragma unroll
        for (int j = 0; j < 8; j++)
            r[j] = *reinterpret_cast<const float4*>(base + (cc + j) * HW);
#pragma unroll
        for (int j = 0; j < 8; j++) {
            int c = cb + cc + j;
            if (r[j].x == 1.f) { f0 = 0.f; g_peak[b*NC+c] = p4;     g_cmask[b*NC+c] = 1.f; }
            if (r[j].y == 1.f) { f1 = 0.f; g_peak[b*NC+c] = p4 + 1; g_cmask[b*NC+c] = 1.f; }
            if (r[j].z == 1.f) { f2 = 0.f; g_peak[b*NC+c] = p4 + 2; g_cmask[b*NC+c] = 1.f; }
            if (r[j].w == 1.f) { f3 = 0.f; g_peak[b*NC+c] = p4 + 3; g_cmask[b*NC+c] = 1.f; }
        }
    }
    f0 *= __shfl_xor_sync(0xffffffffu, f0, 1);
    f1 *= __shfl_xor_sync(0xffffffffu, f1, 1);
    f2 *= __shfl_xor_sync(0xffffffffu, f2, 1);
    f3 *= __shfl_xor_sync(0xffffffffu, f3, 1);
    if (half == 0)
        *reinterpret_cast<float4*>(&g_hmfree[b * HW + p4]) = make_float4(f0, f1, f2, f3);
}

// ---------------------------------------------------------------------------
// Masked per-pixel max/argmax over classes, split across a thread pair
// (40 classes each), combined with first-max semantics (low class wins ties).
__global__ void score_kernel(const float* __restrict__ score) {
    __shared__ float scm[NC];
    int tid  = threadIdx.x;
    int t    = blockIdx.x * blockDim.x + tid;
    int half = t & 1;
    int pair = t >> 1;
    int b    = pair >> 12;
    int p4   = (pair & 4095) << 2;
    int cb   = half * 40;
    if (tid < NC) scm[tid] = g_cmask[b * NC + tid];
    __syncthreads();
    float4 hf = *reinterpret_cast<const float4*>(&g_hmfree[b * HW + p4]);
    const float* base = score + (size_t)b * NC * HW + (size_t)cb * HW + p4;
    float m0 = 0.f, m1 = 0.f, m2 = 0.f, m3 = 0.f;
    int   c0 = 0,   c1 = 0,   c2 = 0,   c3 = 0;
#pragma unroll 1
    for (int cc = 0; cc < 40; cc += 8) {
        float4 r[8];
#pragma unroll
        for (int j = 0; j < 8; j++)
            r[j] = *reinterpret_cast<const float4*>(base + (cc + j) * HW);
#pragma unroll
        for (int j = 0; j < 8; j++) {
            int c = cb + cc + j;
            float cm = scm[c];
            float s0 = r[j].x * cm * hf.x; if (s0 > m0) { m0 = s0; c0 = c; }
            float s1 = r[j].y * cm * hf.y; if (s1 > m1) { m1 = s1; c1 = c; }
            float s2 = r[j].z * cm * hf.z; if (s2 > m2) { m2 = s2; c2 = c; }
            float s3 = r[j].w * cm * hf.w; if (s3 > m3) { m3 = s3; c3 = c; }
        }
    }
    // Combine pair halves. Global first-max: high half wins only on strict >.
    float om; int oc;
    om = __shfl_xor_sync(0xffffffffu, m0, 1); oc = __shfl_xor_sync(0xffffffffu, c0, 1);
    if (half == 0) { if (om > m0) { m0 = om; c0 = oc; } } else { if (!(m0 > om)) { m0 = om; c0 = oc; } }
    om = __shfl_xor_sync(0xffffffffu, m1, 1); oc = __shfl_xor_sync(0xffffffffu, c1, 1);
    if (half == 0) { if (om > m1) { m1 = om; c1 = oc; } } else { if (!(m1 > om)) { m1 = om; c1 = oc; } }
    om = __shfl_xor_sync(0xffffffffu, m2, 1); oc = __shfl_xor_sync(0xffffffffu, c2, 1);
    if (half == 0) { if (om > m2) { m2 = om; c2 = oc; } } else { if (!(m2 > om)) { m2 = om; c2 = oc; } }
    om = __shfl_xor_sync(0xffffffffu, m3, 1); oc = __shfl_xor_sync(0xffffffffu, c3, 1);
    if (half == 0) { if (om > m3) { m3 = om; c3 = oc; } } else { if (!(m3 > om)) { m3 = om; c3 = oc; } }
    if (half == 0)
        *reinterpret_cast<float4*>(&g_maxval[b * HW + p4]) = make_float4(m0, m1, m2, m3);
    else
        *reinterpret_cast<int4*>(&g_argcls[b * HW + p4])   = make_int4(c0, c1, c2, c3);
}

// ---------------------------------------------------------------------------
// Exact top-128 per batch via 3-round radix select on the float bit pattern
// (values >= 0, so uint order == float order). Rounds: bits[20:30) (1024 bins,
// digit <= 1015 since v < 1.0), bits[8:20) (4096), bits[0:8) (256).
// Histogram atomics aggregated per-warp with __match_any_sync.
__global__ void topk_kernel() {
    const int b = blockIdx.x;
    const int tid = threadIdx.x, lane = tid & 31, wid = tid >> 5;  // 16 warps
    const unsigned* mv = reinterpret_cast<const unsigned*>(g_maxval) + b * HW;
    unsigned v[32];
#pragma unroll
    for (int i = 0; i < 32; i++) v[i] = mv[i * 512 + tid];

    __shared__ int hist[4096];
    __shared__ int s_warp[16];
    __shared__ int s_digit, s_K;

    unsigned prefix = 0;
    int K = TOPK;

    // round: nbins bins starting scan at startBase; digit/pred as lambdas
    auto doRound = [&](int nbins, int startBase, int shift, auto digitOf, auto predOf) {
        for (int i = tid; i < nbins; i += 512) hist[i] = 0;
        __syncthreads();
#pragma unroll 1
        for (int i = 0; i < 32; i++) {
            bool pr = predOf(v[i]);
            unsigned amask = __ballot_sync(0xffffffffu, pr);
            if (pr) {
                int d = digitOf(v[i]);
                unsigned mm = __match_any_sync(amask, d);
                if ((__ffs(mm) - 1) == lane) atomicAdd(&hist[d], __popc(mm));
            }
        }
        __syncthreads();
        if (wid == 0) {
            int cum = 0;
            for (int base = startBase; base >= 0; base -= 32) {
                int h = hist[base + lane];
                int s = h;
#pragma unroll
                for (int o = 1; o < 32; o <<= 1) {
                    int t2 = __shfl_down_sync(0xffffffffu, s, o);
                    if (lane + o < 32) s += t2;   // suffix sum lane..31
                }
                int gsum = __shfl_sync(0xffffffffu, s, 0);
                unsigned m2 = __ballot_sync(0xffffffffu, (cum + s) >= K);
                if (m2) {
                    int dl = 31 - __clz(m2);     // largest digit meeting K
                    int sD = __shfl_sync(0xffffffffu, s, dl);
                    int hD = __shfl_sync(0xffffffffu, h, dl);
                    if (lane == 0) {
                        s_digit = base + dl;
                        s_K = K - (cum + sD - hD);
                    }
                    break;
                }
                cum += gsum;
            }
        }
        __syncthreads();
        prefix |= ((unsigned)s_digit) << shift;
        K = s_K;
        __syncthreads();
    };

    doRound(1024, 992, 20,
            [] (unsigned x) { return (int)(x >> 20); },
            [] (unsigned)   { return true; });
    doRound(4096, 4064, 8,
            [] (unsigned x) { return (int)((x >> 8) & 0xFFFu); },
            [&](unsigned x) { return (x >> 20) == (prefix >> 20); });
    doRound(256, 224, 0,
            [] (unsigned x) { return (int)(x & 0xFFu); },
            [&](unsigned x) { return (x >> 8) == (prefix >> 8); });

    unsigned V = prefix;     // exact 128th-largest value
    int En = K;              // needed among == V
    int G  = TOPK - En;      // strictly greater count

    auto scanExcl = [&](int x) -> int {
        __syncthreads();
        int incl = x;
#pragma unroll
        for (int o = 1; o < 32; o <<= 1) {
            int t2 = __shfl_up_sync(0xffffffffu, incl, o);
            if (lane >= o) incl += t2;
        }
        if (lane == 31) s_warp[wid] = incl;
        __syncthreads();
        if (tid < 16) {
            int t2 = s_warp[tid];
            int inc2 = t2;
#pragma unroll
            for (int o = 1; o < 16; o <<= 1) {
                int u = __shfl_up_sync(0x0000ffffu, inc2, o);
                if (tid >= o) inc2 += u;
            }
            s_warp[tid] = inc2 - t2;   // exclusive warp offsets
        }
        __syncthreads();
        return s_warp[wid] + incl - x;
    };

    // Compact > V (deterministic order: reg index major, then tid)
    int cgt = 0;
#pragma unroll
    for (int i = 0; i < 32; i++) cgt += (v[i] > V);
    int slot = scanExcl(cgt);
#pragma unroll
    for (int i = 0; i < 32; i++) {
        if (v[i] > V) {
            int idx = i * 512 + tid;
            g_topk_val[b * TOPK + slot] = __uint_as_float(v[i]);
            g_topk_idx[b * TOPK + slot] = idx;
            g_topk_cls[b * TOPK + slot] = g_argcls[b * HW + idx];
            slot++;
        }
    }
    // Fill remaining with == V entries (first En in deterministic order)
    int ceq = 0;
#pragma unroll
    for (int i = 0; i < 32; i++) ceq += (v[i] == V);
    int r = scanExcl(ceq);
#pragma unroll
    for (int i = 0; i < 32; i++) {
        if (v[i] == V) {
            if (r < En) {
                int idx = i * 512 + tid;
                int s2 = G + r;
                g_topk_val[b * TOPK + s2] = __uint_as_float(v[i]);
                g_topk_idx[b * TOPK + s2] = idx;
                g_topk_cls[b * TOPK + s2] = g_argcls[b * HW + idx];
            }
            r++;
        }
    }
}

// ---------------------------------------------------------------------------
// Gather + L2-normalize feat at peaks (-> q, == k0) and topk pixels (-> ktop).
// One warp per slot; lane handles channels lane and lane+32.
// Also fuses the pseudo_hm scatter (lane 0 of topk slots writes 0.9).
__global__ void gather_kernel(const float* __restrict__ feat, float* __restrict__ out) {
    int gw   = (blockIdx.x * blockDim.x + threadIdx.x) >> 5;
    int lane = threadIdx.x & 31;
    if (gw >= BS * NKEY) return;
    int b = gw / NKEY, s = gw % NKEY;
    float* dst;
    int p;
    if (s < NC) {
        p   = g_peak[b * NC + s];
        dst = g_q + (b * NC + s) * C;
        if (p < 0) { dst[lane] = 0.f; dst[lane + 32] = 0.f; return; }
    } else {
        int j = s - NC;
        p   = g_topk_idx[b * TOPK + j];
        dst = g_ktop + (b * TOPK + j) * C;
        if (lane == 0 && g_topk_val[b * TOPK + j] > 0.f) {
            out[1 + ((size_t)(b * NC + g_topk_cls[b * TOPK + j])) * HW + p] = 0.9f;
        }
    }
    const float* fp = feat + (size_t)b * C * HW + p;
    float a  = fp[(size_t)lane * HW];
    float b2 = fp[(size_t)(lane + 32) * HW];
    float ss = a * a + b2 * b2;
#pragma unroll
    for (int o = 16; o; o >>= 1) ss += __shfl_xor_sync(0xffffffffu, ss, o);
    float inv = 1.f / fmaxf(sqrtf(ss), 1e-12f);
    dst[lane]      = a  * inv;
    dst[lane + 32] = b2 * inv;
}

// ---------------------------------------------------------------------------
// Contrastive loss. Block = (batch, group of 8 classes). Keys staged in SMEM
// in two chunks (128 ktop rows, then 80 q rows == k0) so static SMEM < 48KB.
// log(sim_j / sim_sum) = d_j/tau - log(sim_sum).
__global__ void loss_kernel() {
    __shared__ float ks[TOPK * C];      // 32 KB (reused for both chunks)
    __shared__ float qs[8 * C];         // 2 KB
    __shared__ float r_s[8], r_d[8], r_n[8];
    __shared__ float acc_s[8], acc_d[8], acc_n[8];
    int b   = blockIdx.x / 10;
    int ng  = blockIdx.x % 10;          // classes [ng*8, ng*8+8)
    int tid = threadIdx.x, lane = tid & 31, wid = tid >> 5;

    const float* qb = g_q + b * NC * C;
    for (int i = tid; i < 8 * C; i += 256) qs[i] = qb[ng * 8 * C + i];

    // ---- chunk A: 128 topk keys ----
    const float* kt = g_ktop + b * TOPK * C;
    for (int i = tid; i < TOPK * C; i += 256) ks[i] = kt[i];
    float mallA = 0.f, kvalA = 0.f; int kclsA = -1;
    if (tid < TOPK) {
        kvalA = g_topk_val[b * TOPK + tid];
        mallA = (kvalA > 0.f) ? 1.f : 0.f;
        kclsA = g_topk_cls[b * TOPK + tid];
    }
    __syncthreads();
    for (int nl = 0; nl < 8; nl++) {
        int n = ng * 8 + nl;
        float ssum = 0.f, dsum = 0.f, num = 0.f;
        if (tid < TOPK) {
            float d = 0.f;
            const float* kr = ks + tid * C;
            const float* qr = qs + nl * C;
#pragma unroll
            for (int c = 0; c < C; c++) {
                int cc = (c + tid) & (C - 1);
                d += kr[cc] * qr[cc];
            }
            float dt = d / 0.07f;
            float mm = (kclsA == n && kvalA > 0.f) ? 1.f : 0.f;
            ssum = expf(dt) * mallA;
            dsum = dt * mm;
            num  = mm;
        }
        for (int o = 16; o; o >>= 1) {
            ssum += __shfl_xor_sync(0xffffffffu, ssum, o);
            dsum += __shfl_xor_sync(0xffffffffu, dsum, o);
            num  += __shfl_xor_sync(0xffffffffu, num,  o);
        }
        if (lane == 0) { r_s[wid] = ssum; r_d[wid] = dsum; r_n[wid] = num; }
        __syncthreads();
        if (tid == 0) {
            float S = 0.f, D = 0.f, N = 0.f;
            for (int w = 0; w < 8; w++) { S += r_s[w]; D += r_d[w]; N += r_n[w]; }
            acc_s[nl] = S; acc_d[nl] = D; acc_n[nl] = N;
        }
        __syncthreads();
    }

    // ---- chunk B: 80 k0 keys (== q rows) ----
    for (int i = tid; i < NC * C; i += 256) ks[i] = qb[i];
    float mallB = 0.f;
    if (tid < NC) mallB = g_cmask[b * NC + tid];
    __syncthreads();
    for (int nl = 0; nl < 8; nl++) {
        int n = ng * 8 + nl;
        float cm = g_cmask[b * NC + n];
        float ssum = 0.f, dsum = 0.f, num = 0.f;
        if (tid < NC) {
            float d = 0.f;
            const float* kr = ks + tid * C;
            const float* qr = qs + nl * C;
#pragma unroll
            for (int c = 0; c < C; c++) {
                int cc = (c + tid) & (C - 1);
                d += kr[cc] * qr[cc];
            }
            float dt = d / 0.07f;
            float mm = (tid == n) ? cm : 0.f;   // k0_mask diagonal
            ssum = expf(dt) * mallB;
            dsum = dt * mm;
            num  = mm;
        }
        for (int o = 16; o; o >>= 1) {
            ssum += __shfl_xor_sync(0xffffffffu, ssum, o);
            dsum += __shfl_xor_sync(0xffffffffu, dsum, o);
            num  += __shfl_xor_sync(0xffffffffu, num,  o);
        }
        if (lane == 0) { r_s[wid] = ssum; r_d[wid] = dsum; r_n[wid] = num; }
        __syncthreads();
        if (tid == 0) {
            float S = acc_s[nl], D = acc_d[nl], N = acc_n[nl];
            for (int w = 0; w < 8; w++) { S += r_s[w]; D += r_d[w]; N += r_n[w]; }
            float outv = 0.f;
            if (cm != 0.f) outv = (D - N * logf(S)) / N;  // N >= 1 (diagonal)
            g_contrib[b * NC + n] = outv;
        }
        __syncthreads();
    }
}

// ---------------------------------------------------------------------------
__global__ void final_kernel(float* __restrict__ out) {
    __shared__ float rs[8], rc[8];
    int tid = threadIdx.x, lane = tid & 31, wid = tid >> 5;
    float s = 0.f, c = 0.f;
    for (int i = tid; i < BS * NC; i += 256) { s += g_contrib[i]; c += g_cmask[i]; }
    for (int o = 16; o; o >>= 1) {
        s += __shfl_xor_sync(0xffffffffu, s, o);
        c += __shfl_xor_sync(0xffffffffu, c, o);
    }
    if (lane == 0) { rs[wid] = s; rc[wid] = c; }
    __syncthreads();
    if (tid == 0) {
        float S = 0.f, Cc = 0.f;
        for (int w = 0; w < 8; w++) { S += rs[w]; Cc += rc[w]; }
        out[0] = -(S / Cc);
    }
}

// ---------------------------------------------------------------------------
extern "C" void kernel_launch(void* const* d_in, const int* in_sizes, int n_in,
                              void* d_out, int out_size) {
    const float* feat  = (const float*)d_in[0];
    const float* score = (const float*)d_in[1];
    const float* hm    = (const float*)d_in[2];
    float* out = (float*)d_out;

    // Output layout: [ -loss (1 float), pseudo_hm (16*80*128*128 floats) ]
    cudaMemsetAsync(d_out, 0, (size_t)out_size * sizeof(float), 0);

    init_kernel<<<(BS * NC + 255) / 256, 256>>>();
    hm_kernel<<<BS * (HW / 4) * 2 / 256, 256>>>(hm);
    score_kernel<<<BS * (HW / 4) * 2 / 256, 256>>>(score);
    topk_kernel<<<BS, 512>>>();
    gather_kernel<<<(BS * NKEY * 32 + 255) / 256, 256>>>(feat, out);
    loss_kernel<<<BS * 10, 256>>>();
    final_kernel<<<1, 256>>>(out);
}

// round 6
// speedup vs baseline: 1.0573x; 1.0573x over previous
#include <cuda_runtime.h>
#include <cuda_bf16.h>
#include <cstdint>
#include <math.h>

// Problem constants
constexpr int BS = 16, C = 64, H = 128, W = 128;
constexpr int HW = H * W;           // 16384
constexpr int NC = 80;
constexpr int TOPK = 128;
constexpr int NKEY = TOPK + NC;     // 208

// Scratch (device globals; no allocation allowed)
__device__ int   g_peak[BS * NC];
__device__ float g_cmask[BS * NC];
__device__ float g_hmfree[BS * HW];
__device__ float g_maxval[BS * HW];
__device__ int   g_argcls[BS * HW];
__device__ int   g_topk_idx[BS * TOPK];
__device__ float g_topk_val[BS * TOPK];
__device__ int   g_topk_cls[BS * TOPK];
__device__ float g_q[BS * NC * C];
__device__ float g_ktop[BS * TOPK * C];
__device__ float g_contrib[BS * NC];

// ---------------------------------------------------------------------------
__global__ void init_kernel() {
    int t = blockIdx.x * blockDim.x + threadIdx.x;
    if (t < BS * NC) { g_peak[t] = -1; g_cmask[t] = 0.f; }
}

// ---------------------------------------------------------------------------
// Scan hm: find peak position per (b,c), class_mask, and per-pixel hm_free.
// Thread handles 4 consecutive pixels (float4); 8-deep prefetch for MLP.
__global__ void hm_kernel(const float* __restrict__ hm) {
    int t  = blockIdx.x * blockDim.x + threadIdx.x;
    int b  = t >> 12;
    int p4 = (t & 4095) << 2;
    const float* base = hm + (size_t)b * NC * HW + p4;
    float f0 = 1.f, f1 = 1.f, f2 = 1.f, f3 = 1.f;
#pragma unroll
    for (int cc = 0; cc < NC; cc += 8) {
        float4 r[8];
#pragma unroll
        for (int j = 0; j < 8; j++)
            r[j] = *reinterpret_cast<const float4*>(base + (cc + j) * HW);
#pragma unroll
        for (int j = 0; j < 8; j++) {
            int c = cc + j;
            if (r[j].x == 1.f) { f0 = 0.f; g_peak[b*NC+c] = p4;     g_cmask[b*NC+c] = 1.f; }
            if (r[j].y == 1.f) { f1 = 0.f; g_peak[b*NC+c] = p4 + 1; g_cmask[b*NC+c] = 1.f; }
            if (r[j].z == 1.f) { f2 = 0.f; g_peak[b*NC+c] = p4 + 2; g_cmask[b*NC+c] = 1.f; }
            if (r[j].w == 1.f) { f3 = 0.f; g_peak[b*NC+c] = p4 + 3; g_cmask[b*NC+c] = 1.f; }
        }
    }
    *reinterpret_cast<float4*>(&g_hmfree[b * HW + p4]) = make_float4(f0, f1, f2, f3);
}

// ---------------------------------------------------------------------------
// Masked per-pixel max/argmax over classes. First-max semantics (strict >).
// 8-deep float4 prefetch for MLP.
__global__ void score_kernel(const float* __restrict__ score) {
    __shared__ float scm[NC];
    int b  = blockIdx.x >> 4;
    int p4 = ((((blockIdx.x & 15) << 8) + threadIdx.x)) << 2;
    if (threadIdx.x < NC) scm[threadIdx.x] = g_cmask[b * NC + threadIdx.x];
    __syncthreads();
    float4 hf = *reinterpret_cast<const float4*>(&g_hmfree[b * HW + p4]);
    const float* base = score + (size_t)b * NC * HW + p4;
    float m0 = 0.f, m1 = 0.f, m2 = 0.f, m3 = 0.f;
    int   c0 = 0,   c1 = 0,   c2 = 0,   c3 = 0;
#pragma unroll
    for (int cc = 0; cc < NC; cc += 8) {
        float4 r[8];
#pragma unroll
        for (int j = 0; j < 8; j++)
            r[j] = *reinterpret_cast<const float4*>(base + (cc + j) * HW);
#pragma unroll
        for (int j = 0; j < 8; j++) {
            int c = cc + j;
            float cm = scm[c];
            float s0 = r[j].x * cm * hf.x; if (s0 > m0) { m0 = s0; c0 = c; }
            float s1 = r[j].y * cm * hf.y; if (s1 > m1) { m1 = s1; c1 = c; }
            float s2 = r[j].z * cm * hf.z; if (s2 > m2) { m2 = s2; c2 = c; }
            float s3 = r[j].w * cm * hf.w; if (s3 > m3) { m3 = s3; c3 = c; }
        }
    }
    *reinterpret_cast<float4*>(&g_maxval[b * HW + p4]) = make_float4(m0, m1, m2, m3);
    *reinterpret_cast<int4*>(&g_argcls[b * HW + p4])   = make_int4(c0, c1, c2, c3);
}

// ---------------------------------------------------------------------------
// Exact top-128 per batch: 8-way multi-threshold search on the float bit
// pattern (values >= 0 so uint order == float order). Each iteration counts
// 7 interior thresholds at once (cheap ILP), shrinking the range 8x:
// ~11 wide rounds + <=3 binary rounds + 1 G-pass = ~15 barriers vs 32.
// One block (512 thr) per batch; 32 values/thread.
__global__ void topk_kernel() {
    const int b = blockIdx.x;
    const int tid = threadIdx.x, lane = tid & 31, wid = tid >> 5;  // 16 warps
    const unsigned* mv = reinterpret_cast<const unsigned*>(g_maxval) + b * HW;
    unsigned v[32];
#pragma unroll
    for (int i = 0; i < 32; i++) v[i] = mv[i * 512 + tid];

    __shared__ int s_cnt[160];          // per-iteration count slots (zeroed once)
    __shared__ int s_warp[16];
    for (int i = tid; i < 160; i += 512) s_cnt[i] = 0;
    __syncthreads();

    // Invariant: count(>= lo) >= TOPK (lo=0 trivially: 16384 >= 128),
    //            count(>= hi) <  TOPK (hi=1.0: all values < 1.0).
    unsigned lo = 0, hi = 0x3F800000u;
    int it = 0;

    // Wide 8-way rounds
    while (hi - lo > 8u) {
        unsigned step = (hi - lo) >> 3;
        unsigned T[7];
#pragma unroll
        for (int j = 0; j < 7; j++) T[j] = lo + step * (j + 1);
        int c[7] = {0, 0, 0, 0, 0, 0, 0};
#pragma unroll
        for (int i = 0; i < 32; i++) {
            unsigned x = v[i];
#pragma unroll
            for (int j = 0; j < 7; j++) c[j] += (x >= T[j]);
        }
#pragma unroll
        for (int j = 0; j < 7; j++) {
            int cj = c[j];
#pragma unroll
            for (int o = 16; o; o >>= 1) cj += __shfl_xor_sync(0xffffffffu, cj, o);
            if (lane == 0) atomicAdd(&s_cnt[it * 8 + j], cj);
        }
        __syncthreads();
        int m = 0;
#pragma unroll
        for (int j = 0; j < 7; j++) m += (s_cnt[it * 8 + j] >= TOPK);
        // counts are monotone nonincreasing in T; first m thresholds qualify
        unsigned nlo = m ? T[m - 1] : lo;
        unsigned nhi = (m < 7) ? T[m] : hi;
        lo = nlo; hi = nhi;
        it++;
    }

    // Binary finish (range <= 8)
    while (hi - lo > 1u) {
        unsigned mid = lo + ((hi - lo) >> 1);
        int c = 0;
#pragma unroll
        for (int i = 0; i < 32; i++) c += (v[i] >= mid);
#pragma unroll
        for (int o = 16; o; o >>= 1) c += __shfl_xor_sync(0xffffffffu, c, o);
        if (lane == 0) atomicAdd(&s_cnt[it * 8], c);
        __syncthreads();
        if (s_cnt[it * 8] >= TOPK) lo = mid; else hi = mid;
        it++;
    }
    unsigned V = lo;                 // exact 128th-largest value

    // G = strictly-greater count
    {
        int c = 0;
#pragma unroll
        for (int i = 0; i < 32; i++) c += (v[i] > V);
#pragma unroll
        for (int o = 16; o; o >>= 1) c += __shfl_xor_sync(0xffffffffu, c, o);
        if (lane == 0) atomicAdd(&s_cnt[it * 8], c);
        __syncthreads();
    }
    int G  = s_cnt[it * 8];
    int En = TOPK - G;               // needed among == V

    auto scanExcl = [&](int x) -> int {
        __syncthreads();
        int incl = x;
#pragma unroll
        for (int o = 1; o < 32; o <<= 1) {
            int t2 = __shfl_up_sync(0xffffffffu, incl, o);
            if (lane >= o) incl += t2;
        }
        if (lane == 31) s_warp[wid] = incl;
        __syncthreads();
        if (tid < 16) {
            int t2 = s_warp[tid];
            int inc2 = t2;
#pragma unroll
            for (int o = 1; o < 16; o <<= 1) {
                int u = __shfl_up_sync(0x0000ffffu, inc2, o);
                if (tid >= o) inc2 += u;
            }
            s_warp[tid] = inc2 - t2;   // exclusive warp offsets
        }
        __syncthreads();
        return s_warp[wid] + incl - x;
    };

    // Compact > V (deterministic order: reg index major, then tid)
    int cgt = 0;
#pragma unroll
    for (int i = 0; i < 32; i++) cgt += (v[i] > V);
    int slot = scanExcl(cgt);
#pragma unroll
    for (int i = 0; i < 32; i++) {
        if (v[i] > V) {
            int idx = i * 512 + tid;
            g_topk_val[b * TOPK + slot] = __uint_as_float(v[i]);
            g_topk_idx[b * TOPK + slot] = idx;
            g_topk_cls[b * TOPK + slot] = g_argcls[b * HW + idx];
            slot++;
        }
    }
    // Fill remaining with == V entries (first En in deterministic order)
    int ceq = 0;
#pragma unroll
    for (int i = 0; i < 32; i++) ceq += (v[i] == V);
    int r = scanExcl(ceq);
#pragma unroll
    for (int i = 0; i < 32; i++) {
        if (v[i] == V) {
            if (r < En) {
                int idx = i * 512 + tid;
                int s2 = G + r;
                g_topk_val[b * TOPK + s2] = __uint_as_float(v[i]);
                g_topk_idx[b * TOPK + s2] = idx;
                g_topk_cls[b * TOPK + s2] = g_argcls[b * HW + idx];
            }
            r++;
        }
    }
}

// ---------------------------------------------------------------------------
// Gather + L2-normalize feat at peaks (-> q, == k0) and topk pixels (-> ktop).
// One warp per slot; lane handles channels lane and lane+32.
// Also fuses the pseudo_hm scatter (lane 0 of topk slots writes 0.9).
__global__ void gather_kernel(const float* __restrict__ feat, float* __restrict__ out) {
    int gw   = (blockIdx.x * blockDim.x + threadIdx.x) >> 5;
    int lane = threadIdx.x & 31;
    if (gw >= BS * NKEY) return;
    int b = gw / NKEY, s = gw % NKEY;
    float* dst;
    int p;
    if (s < NC) {
        p   = g_peak[b * NC + s];
        dst = g_q + (b * NC + s) * C;
        if (p < 0) { dst[lane] = 0.f; dst[lane + 32] = 0.f; return; }
    } else {
        int j = s - NC;
        p   = g_topk_idx[b * TOPK + j];
        dst = g_ktop + (b * TOPK + j) * C;
        if (lane == 0 && g_topk_val[b * TOPK + j] > 0.f) {
            out[1 + ((size_t)(b * NC + g_topk_cls[b * TOPK + j])) * HW + p] = 0.9f;
        }
    }
    const float* fp = feat + (size_t)b * C * HW + p;
    float a  = fp[(size_t)lane * HW];
    float b2 = fp[(size_t)(lane + 32) * HW];
    float ss = a * a + b2 * b2;
#pragma unroll
    for (int o = 16; o; o >>= 1) ss += __shfl_xor_sync(0xffffffffu, ss, o);
    float inv = 1.f / fmaxf(sqrtf(ss), 1e-12f);
    dst[lane]      = a  * inv;
    dst[lane + 32] = b2 * inv;
}

// ---------------------------------------------------------------------------
// Contrastive loss. Block = (batch, group of 8 classes). Keys staged in SMEM
// in two chunks (128 ktop rows, then 80 q rows == k0) so static SMEM < 48KB.
// log(sim_j / sim_sum) = d_j/tau - log(sim_sum).
__global__ void loss_kernel() {
    __shared__ float ks[TOPK * C];      // 32 KB (reused for both chunks)
    __shared__ float qs[8 * C];         // 2 KB
    __shared__ float r_s[8], r_d[8], r_n[8];
    __shared__ float acc_s[8], acc_d[8], acc_n[8];
    int b   = blockIdx.x / 10;
    int ng  = blockIdx.x % 10;          // classes [ng*8, ng*8+8)
    int tid = threadIdx.x, lane = tid & 31, wid = tid >> 5;

    const float* qb = g_q + b * NC * C;
    for (int i = tid; i < 8 * C; i += 256) qs[i] = qb[ng * 8 * C + i];

    // ---- chunk A: 128 topk keys ----
    const float* kt = g_ktop + b * TOPK * C;
    for (int i = tid; i < TOPK * C; i += 256) ks[i] = kt[i];
    float mallA = 0.f, kvalA = 0.f; int kclsA = -1;
    if (tid < TOPK) {
        kvalA = g_topk_val[b * TOPK + tid];
        mallA = (kvalA > 0.f) ? 1.f : 0.f;
        kclsA = g_topk_cls[b * TOPK + tid];
    }
    __syncthreads();
    for (int nl = 0; nl < 8; nl++) {
        int n = ng * 8 + nl;
        float ssum = 0.f, dsum = 0.f, num = 0.f;
        if (tid < TOPK) {
            float d = 0.f;
            const float* kr = ks + tid * C;
            const float* qr = qs + nl * C;
#pragma unroll
            for (int c = 0; c < C; c++) {
                int cc = (c + tid) & (C - 1);
                d += kr[cc] * qr[cc];
            }
            float dt = d / 0.07f;
            float mm = (kclsA == n && kvalA > 0.f) ? 1.f : 0.f;
            ssum = expf(dt) * mallA;
            dsum = dt * mm;
            num  = mm;
        }
        for (int o = 16; o; o >>= 1) {
            ssum += __shfl_xor_sync(0xffffffffu, ssum, o);
            dsum += __shfl_xor_sync(0xffffffffu, dsum, o);
            num  += __shfl_xor_sync(0xffffffffu, num,  o);
        }
        if (lane == 0) { r_s[wid] = ssum; r_d[wid] = dsum; r_n[wid] = num; }
        __syncthreads();
        if (tid == 0) {
            float S = 0.f, D = 0.f, N = 0.f;
            for (int w = 0; w < 8; w++) { S += r_s[w]; D += r_d[w]; N += r_n[w]; }
            acc_s[nl] = S; acc_d[nl] = D; acc_n[nl] = N;
        }
        __syncthreads();
    }

    // ---- chunk B: 80 k0 keys (== q rows) ----
    for (int i = tid; i < NC * C; i += 256) ks[i] = qb[i];
    float mallB = 0.f;
    if (tid < NC) mallB = g_cmask[b * NC + tid];
    __syncthreads();
    for (int nl = 0; nl < 8; nl++) {
        int n = ng * 8 + nl;
        float cm = g_cmask[b * NC + n];
        float ssum = 0.f, dsum = 0.f, num = 0.f;
        if (tid < NC) {
            float d = 0.f;
            const float* kr = ks + tid * C;
            const float* qr = qs + nl * C;
#pragma unroll
            for (int c = 0; c < C; c++) {
                int cc = (c + tid) & (C - 1);
                d += kr[cc] * qr[cc];
            }
            float dt = d / 0.07f;
            float mm = (tid == n) ? cm : 0.f;   // k0_mask diagonal
            ssum = expf(dt) * mallB;
            dsum = dt * mm;
            num  = mm;
        }
        for (int o = 16; o; o >>= 1) {
            ssum += __shfl_xor_sync(0xffffffffu, ssum, o);
            dsum += __shfl_xor_sync(0xffffffffu, dsum, o);
            num  += __shfl_xor_sync(0xffffffffu, num,  o);
        }
        if (lane == 0) { r_s[wid] = ssum; r_d[wid] = dsum; r_n[wid] = num; }
        __syncthreads();
        if (tid == 0) {
            float S = acc_s[nl], D = acc_d[nl], N = acc_n[nl];
            for (int w = 0; w < 8; w++) { S += r_s[w]; D += r_d[w]; N += r_n[w]; }
            float outv = 0.f;
            if (cm != 0.f) outv = (D - N * logf(S)) / N;  // N >= 1 (diagonal)
            g_contrib[b * NC + n] = outv;
        }
        __syncthreads();
    }
}

// ---------------------------------------------------------------------------
__global__ void final_kernel(float* __restrict__ out) {
    __shared__ float rs[8], rc[8];
    int tid = threadIdx.x, lane = tid & 31, wid = tid >> 5;
    float s = 0.f, c = 0.f;
    for (int i = tid; i < BS * NC; i += 256) { s += g_contrib[i]; c += g_cmask[i]; }
    for (int o = 16; o; o >>= 1) {
        s += __shfl_xor_sync(0xffffffffu, s, o);
        c += __shfl_xor_sync(0xffffffffu, c, o);
    }
    if (lane == 0) { rs[wid] = s; rc[wid] = c; }
    __syncthreads();
    if (tid == 0) {
        float S = 0.f, Cc = 0.f;
        for (int w = 0; w < 8; w++) { S += rs[w]; Cc += rc[w]; }
        out[0] = -(S / Cc);
    }
}

// ---------------------------------------------------------------------------
extern "C" void kernel_launch(void* const* d_in, const int* in_sizes, int n_in,
                              void* d_out, int out_size) {
    const float* feat  = (const float*)d_in[0];
    const float* score = (const float*)d_in[1];
    const float* hm    = (const float*)d_in[2];
    float* out = (float*)d_out;

    // Output layout: [ -loss (1 float), pseudo_hm (16*80*128*128 floats) ]
    cudaMemsetAsync(d_out, 0, (size_t)out_size * sizeof(float), 0);

    init_kernel<<<(BS * NC + 255) / 256, 256>>>();
    hm_kernel<<<BS * (HW / 4) / 256, 256>>>(hm);
    score_kernel<<<BS * 16, 256>>>(score);
    topk_kernel<<<BS, 512>>>();
    gather_kernel<<<(BS * NKEY * 32 + 255) / 256, 256>>>(feat, out);
    loss_kernel<<<BS * 10, 256>>>();
    final_kernel<<<1, 256>>>(out);
}

// round 8
// speedup vs baseline: 1.1590x; 1.0963x over previous
#include <cuda_runtime.h>
#include <cuda_bf16.h>
#include <cstdint>
#include <math.h>

// Problem constants
constexpr int BS = 16, C = 64, H = 128, W = 128;
constexpr int HW = H * W;           // 16384
constexpr int NC = 80;
constexpr int TOPK = 128;
constexpr int NKEY = TOPK + NC;     // 208
constexpr int CAP = 4096;           // candidate buffer per batch
constexpr float CAND_T = 0.999f;    // prefilter threshold

// Scratch (device globals; no allocation allowed)
__device__ int                g_peak[BS * NC];
__device__ float              g_cmask[BS * NC];
__device__ float              g_hmfree[BS * HW];
__device__ float              g_maxval[BS * HW];
__device__ int                g_argcls[BS * HW];
__device__ int                g_ccount[BS];
__device__ unsigned long long g_cand[BS * CAP];
__device__ int                g_cand_cls[BS * CAP];
__device__ int                g_topk_idx[BS * TOPK];
__device__ float              g_topk_val[BS * TOPK];
__device__ int                g_topk_cls[BS * TOPK];
__device__ float              g_q[BS * NC * C];
__device__ float              g_ktop[BS * TOPK * C];
__device__ float              g_contrib[BS * NC];

// ---------------------------------------------------------------------------
__global__ void init_kernel() {
    int t = blockIdx.x * blockDim.x + threadIdx.x;
    if (t < BS * NC) { g_peak[t] = -1; g_cmask[t] = 0.f; }
    if (t < BS) g_ccount[t] = 0;
}

// ---------------------------------------------------------------------------
// Scan hm: find peak position per (b,c), class_mask, and per-pixel hm_free.
// Thread handles 4 consecutive pixels (float4); 8-deep prefetch for MLP.
__global__ void hm_kernel(const float* __restrict__ hm) {
    int t  = blockIdx.x * blockDim.x + threadIdx.x;
    int b  = t >> 12;
    int p4 = (t & 4095) << 2;
    const float* base = hm + (size_t)b * NC * HW + p4;
    float f0 = 1.f, f1 = 1.f, f2 = 1.f, f3 = 1.f;
#pragma unroll
    for (int cc = 0; cc < NC; cc += 8) {
        float4 r[8];
#pragma unroll
        for (int j = 0; j < 8; j++)
            r[j] = *reinterpret_cast<const float4*>(base + (cc + j) * HW);
#pragma unroll
        for (int j = 0; j < 8; j++) {
            int c = cc + j;
            if (r[j].x == 1.f) { f0 = 0.f; g_peak[b*NC+c] = p4;     g_cmask[b*NC+c] = 1.f; }
            if (r[j].y == 1.f) { f1 = 0.f; g_peak[b*NC+c] = p4 + 1; g_cmask[b*NC+c] = 1.f; }
            if (r[j].z == 1.f) { f2 = 0.f; g_peak[b*NC+c] = p4 + 2; g_cmask[b*NC+c] = 1.f; }
            if (r[j].w == 1.f) { f3 = 0.f; g_peak[b*NC+c] = p4 + 3; g_cmask[b*NC+c] = 1.f; }
        }
    }
    *reinterpret_cast<float4*>(&g_hmfree[b * HW + p4]) = make_float4(f0, f1, f2, f3);
}

// ---------------------------------------------------------------------------
// Masked per-pixel max/argmax over classes (first-max semantics), PLUS:
//  - candidate prefilter (maxval >= CAND_T -> packed candidate list)
//  - zeroing of the output buffer (replaces the separate memset pass)
__device__ __forceinline__ void add_candidate(int b, float m, int idx, int cls) {
    if (m >= CAND_T) {
        int pos = atomicAdd(&g_ccount[b], 1);
        if (pos < CAP) {
            unsigned vb = __float_as_uint(m);
            g_cand[b * CAP + pos] =
                ((unsigned long long)vb << 14) | (unsigned)(16383 - idx);
            g_cand_cls[b * CAP + pos] = cls;
        }
    }
}

__global__ void score_kernel(const float* __restrict__ score,
                             float* __restrict__ out, int out_size) {
    __shared__ float scm[NC];
    int b  = blockIdx.x >> 4;
    int p4 = ((((blockIdx.x & 15) << 8) + threadIdx.x)) << 2;
    if (threadIdx.x < NC) scm[threadIdx.x] = g_cmask[b * NC + threadIdx.x];
    __syncthreads();
    float4 hf = *reinterpret_cast<const float4*>(&g_hmfree[b * HW + p4]);
    const float* base = score + (size_t)b * NC * HW + p4;
    float m0 = 0.f, m1 = 0.f, m2 = 0.f, m3 = 0.f;
    int   c0 = 0,   c1 = 0,   c2 = 0,   c3 = 0;
#pragma unroll
    for (int cc = 0; cc < NC; cc += 8) {
        float4 r[8];
#pragma unroll
        for (int j = 0; j < 8; j++)
            r[j] = *reinterpret_cast<const float4*>(base + (cc + j) * HW);
#pragma unroll
        for (int j = 0; j < 8; j++) {
            int c = cc + j;
            float cm = scm[c];
            float s0 = r[j].x * cm * hf.x; if (s0 > m0) { m0 = s0; c0 = c; }
            float s1 = r[j].y * cm * hf.y; if (s1 > m1) { m1 = s1; c1 = c; }
            float s2 = r[j].z * cm * hf.z; if (s2 > m2) { m2 = s2; c2 = c; }
            float s3 = r[j].w * cm * hf.w; if (s3 > m3) { m3 = s3; c3 = c; }
        }
    }
    *reinterpret_cast<float4*>(&g_maxval[b * HW + p4]) = make_float4(m0, m1, m2, m3);
    *reinterpret_cast<int4*>(&g_argcls[b * HW + p4])   = make_int4(c0, c1, c2, c3);

    add_candidate(b, m0, p4,     c0);
    add_candidate(b, m1, p4 + 1, c1);
    add_candidate(b, m2, p4 + 2, c2);
    add_candidate(b, m3, p4 + 3, c3);

    // Zero the output buffer (grid-stride float4 across all 256 blocks).
    int   gtid = blockIdx.x * 256 + threadIdx.x;
    int   n4   = out_size >> 2;
    float4* o4 = reinterpret_cast<float4*>(out);
    const float4 z4 = make_float4(0.f, 0.f, 0.f, 0.f);
    for (int i = gtid; i < n4; i += 256 * 256) o4[i] = z4;
    if (gtid == 0)
        for (int i = n4 << 2; i < out_size; i++) out[i] = 0.f;
}

// ---------------------------------------------------------------------------
// Exact top-128 from the candidate list: pairwise rank count over M packed
// (value, 16383-idx) keys in smem -> rank r < 128 writes slot r directly.
// Deterministic and order-independent; matches jax top_k tie semantics
// (equal value -> lower pixel index first). Fallback to full binary search
// if the prefilter under/overflowed (not expected on this data).
__global__ void cand_kernel() {
    const int b = blockIdx.x;
    const int tid = threadIdx.x, lane = tid & 31, wid = tid >> 5;  // 32 warps
    __shared__ unsigned long long sp[CAP];   // 32 KB
    int M = g_ccount[b];

    if (M >= TOPK && M <= CAP) {
        for (int i = tid; i < M; i += 1024) sp[i] = g_cand[b * CAP + i];
        __syncthreads();
        for (int i = tid; i < M; i += 1024) {
            unsigned long long me = sp[i];
            int r = 0;
            for (int j = 0; j < M; j++) r += (sp[j] > me);
            if (r < TOPK) {
                unsigned vb = (unsigned)(me >> 14);
                int idx = 16383 - (int)(me & 16383u);
                g_topk_val[b * TOPK + r] = __uint_as_float(vb);
                g_topk_idx[b * TOPK + r] = idx;
                g_topk_cls[b * TOPK + r] = g_cand_cls[b * CAP + i];
            }
        }
        return;
    }

    // ---- Fallback: exact binary search on float bits over all 16384 ----
    const unsigned* mv = reinterpret_cast<const unsigned*>(g_maxval) + b * HW;
    unsigned v[16];
#pragma unroll
    for (int i = 0; i < 16; i++) v[i] = mv[i * 1024 + tid];

    __shared__ int s_warp[32];
    __shared__ int s_tot;

    auto blockCount = [&](unsigned thr, bool strict) -> int {
        __syncthreads();
        int c = 0;
#pragma unroll
        for (int i = 0; i < 16; i++) c += strict ? (v[i] > thr) : (v[i] >= thr);
        for (int o = 16; o; o >>= 1) c += __shfl_xor_sync(0xffffffffu, c, o);
        if (lane == 0) s_warp[wid] = c;
        __syncthreads();
        if (tid < 32) {
            int t2 = s_warp[tid];
            for (int o = 16; o; o >>= 1) t2 += __shfl_xor_sync(0xffffffffu, t2, o);
            if (tid == 0) s_tot = t2;
        }
        __syncthreads();
        return s_tot;
    };

    auto blockScanExcl = [&](int x) -> int {
        __syncthreads();
        int incl = x;
        for (int o = 1; o < 32; o <<= 1) {
            int t2 = __shfl_up_sync(0xffffffffu, incl, o);
            if (lane >= o) incl += t2;
        }
        if (lane == 31) s_warp[wid] = incl;
        __syncthreads();
        if (tid < 32) {
            int t2 = s_warp[tid];
            int inc2 = t2;
            for (int o = 1; o < 32; o <<= 1) {
                int u = __shfl_up_sync(0xffffffffu, inc2, o);
                if (tid >= o) inc2 += u;
            }
            s_warp[tid] = inc2 - t2;
        }
        __syncthreads();
        return s_warp[wid] + incl - x;
    };

    unsigned lo = 0, hi = 0x3F800000u;
    while (lo < hi) {
        unsigned mid = lo + ((hi - lo + 1) >> 1);
        int c = blockCount(mid, false);
        if (c >= TOPK) lo = mid; else hi = mid - 1;
    }
    unsigned V = lo;
    int G  = blockCount(V, true);
    int En = TOPK - G;

    int cgt = 0;
#pragma unroll
    for (int i = 0; i < 16; i++) cgt += (v[i] > V);
    int slot = blockScanExcl(cgt);
#pragma unroll
    for (int i = 0; i < 16; i++) {
        if (v[i] > V) {
            int idx = i * 1024 + tid;
            g_topk_val[b * TOPK + slot] = __uint_as_float(v[i]);
            g_topk_idx[b * TOPK + slot] = idx;
            g_topk_cls[b * TOPK + slot] = g_argcls[b * HW + idx];
            slot++;
        }
    }
    int ceq = 0;
#pragma unroll
    for (int i = 0; i < 16; i++) ceq += (v[i] == V);
    int r = blockScanExcl(ceq);
#pragma unroll
    for (int i = 0; i < 16; i++) {
        if (v[i] == V) {
            if (r < En) {
                int idx = i * 1024 + tid;
                int s2 = G + r;
                g_topk_val[b * TOPK + s2] = __uint_as_float(v[i]);
                g_topk_idx[b * TOPK + s2] = idx;
                g_topk_cls[b * TOPK + s2] = g_argcls[b * HW + idx];
            }
            r++;
        }
    }
}

// ---------------------------------------------------------------------------
// Gather + L2-normalize feat at peaks (-> q, == k0) and topk pixels (-> ktop).
// One warp per slot; lane handles channels lane and lane+32.
// Also fuses the pseudo_hm scatter (lane 0 of topk slots writes 0.9).
__global__ void gather_kernel(const float* __restrict__ feat, float* __restrict__ out) {
    int gw   = (blockIdx.x * blockDim.x + threadIdx.x) >> 5;
    int lane = threadIdx.x & 31;
    if (gw >= BS * NKEY) return;
    int b = gw / NKEY, s = gw % NKEY;
    float* dst;
    int p;
    if (s < NC) {
        p   = g_peak[b * NC + s];
        dst = g_q + (b * NC + s) * C;
        if (p < 0) { dst[lane] = 0.f; dst[lane + 32] = 0.f; return; }
    } else {
        int j = s - NC;
        p   = g_topk_idx[b * TOPK + j];
        dst = g_ktop + (b * TOPK + j) * C;
        if (lane == 0 && g_topk_val[b * TOPK + j] > 0.f) {
            out[1 + ((size_t)(b * NC + g_topk_cls[b * TOPK + j])) * HW + p] = 0.9f;
        }
    }
    const float* fp = feat + (size_t)b * C * HW + p;
    float a  = fp[(size_t)lane * HW];
    float b2 = fp[(size_t)(lane + 32) * HW];
    float ss = a * a + b2 * b2;
#pragma unroll
    for (int o = 16; o; o >>= 1) ss += __shfl_xor_sync(0xffffffffu, ss, o);
    float inv = 1.f / fmaxf(sqrtf(ss), 1e-12f);
    dst[lane]      = a  * inv;
    dst[lane + 32] = b2 * inv;
}

// ---------------------------------------------------------------------------
// Contrastive loss. Block = (batch, group of 8 classes). Keys staged in SMEM
// in two chunks (128 ktop rows, then 80 q rows == k0) so static SMEM < 48KB.
// log(sim_j / sim_sum) = d_j/tau - log(sim_sum).
__global__ void loss_kernel() {
    __shared__ float ks[TOPK * C];      // 32 KB (reused for both chunks)
    __shared__ float qs[8 * C];         // 2 KB
    __shared__ float r_s[8], r_d[8], r_n[8];
    __shared__ float acc_s[8], acc_d[8], acc_n[8];
    int b   = blockIdx.x / 10;
    int ng  = blockIdx.x % 10;          // classes [ng*8, ng*8+8)
    int tid = threadIdx.x, lane = tid & 31, wid = tid >> 5;

    const float* qb = g_q + b * NC * C;
    for (int i = tid; i < 8 * C; i += 256) qs[i] = qb[ng * 8 * C + i];

    // ---- chunk A: 128 topk keys ----
    const float* kt = g_ktop + b * TOPK * C;
    for (int i = tid; i < TOPK * C; i += 256) ks[i] = kt[i];
    float mallA = 0.f, kvalA = 0.f; int kclsA = -1;
    if (tid < TOPK) {
        kvalA = g_topk_val[b * TOPK + tid];
        mallA = (kvalA > 0.f) ? 1.f : 0.f;
        kclsA = g_topk_cls[b * TOPK + tid];
    }
    __syncthreads();
    for (int nl = 0; nl < 8; nl++) {
        int n = ng * 8 + nl;
        float ssum = 0.f, dsum = 0.f, num = 0.f;
        if (tid < TOPK) {
            float d = 0.f;
            const float* kr = ks + tid * C;
            const float* qr = qs + nl * C;
#pragma unroll
            for (int c = 0; c < C; c++) {
                int cc = (c + tid) & (C - 1);
                d += kr[cc] * qr[cc];
            }
            float dt = d / 0.07f;
            float mm = (kclsA == n && kvalA > 0.f) ? 1.f : 0.f;
            ssum = expf(dt) * mallA;
            dsum = dt * mm;
            num  = mm;
        }
        for (int o = 16; o; o >>= 1) {
            ssum += __shfl_xor_sync(0xffffffffu, ssum, o);
            dsum += __shfl_xor_sync(0xffffffffu, dsum, o);
            num  += __shfl_xor_sync(0xffffffffu, num,  o);
        }
        if (lane == 0) { r_s[wid] = ssum; r_d[wid] = dsum; r_n[wid] = num; }
        __syncthreads();
        if (tid == 0) {
            float S = 0.f, D = 0.f, N = 0.f;
            for (int w = 0; w < 8; w++) { S += r_s[w]; D += r_d[w]; N += r_n[w]; }
            acc_s[nl] = S; acc_d[nl] = D; acc_n[nl] = N;
        }
        __syncthreads();
    }

    // ---- chunk B: 80 k0 keys (== q rows) ----
    for (int i = tid; i < NC * C; i += 256) ks[i] = qb[i];
    float mallB = 0.f;
    if (tid < NC) mallB = g_cmask[b * NC + tid];
    __syncthreads();
    for (int nl = 0; nl < 8; nl++) {
        int n = ng * 8 + nl;
        float cm = g_cmask[b * NC + n];
        float ssum = 0.f, dsum = 0.f, num = 0.f;
        if (tid < NC) {
            float d = 0.f;
            const float* kr = ks + tid * C;
            const float* qr = qs + nl * C;
#pragma unroll
            for (int c = 0; c < C; c++) {
                int cc = (c + tid) & (C - 1);
                d += kr[cc] * qr[cc];
            }
            float dt = d / 0.07f;
            float mm = (tid == n) ? cm : 0.f;   // k0_mask diagonal
            ssum = expf(dt) * mallB;
            dsum = dt * mm;
            num  = mm;
        }
        for (int o = 16; o; o >>= 1) {
            ssum += __shfl_xor_sync(0xffffffffu, ssum, o);
            dsum += __shfl_xor_sync(0xffffffffu, dsum, o);
            num  += __shfl_xor_sync(0xffffffffu, num,  o);
        }
        if (lane == 0) { r_s[wid] = ssum; r_d[wid] = dsum; r_n[wid] = num; }
        __syncthreads();
        if (tid == 0) {
            float S = acc_s[nl], D = acc_d[nl], N = acc_n[nl];
            for (int w = 0; w < 8; w++) { S += r_s[w]; D += r_d[w]; N += r_n[w]; }
            float outv = 0.f;
            if (cm != 0.f) outv = (D - N * logf(S)) / N;  // N >= 1 (diagonal)
            g_contrib[b * NC + n] = outv;
        }
        __syncthreads();
    }
}

// ---------------------------------------------------------------------------
__global__ void final_kernel(float* __restrict__ out) {
    __shared__ float rs[8], rc[8];
    int tid = threadIdx.x, lane = tid & 31, wid = tid >> 5;
    float s = 0.f, c = 0.f;
    for (int i = tid; i < BS * NC; i += 256) { s += g_contrib[i]; c += g_cmask[i]; }
    for (int o = 16; o; o >>= 1) {
        s += __shfl_xor_sync(0xffffffffu, s, o);
        c += __shfl_xor_sync(0xffffffffu, c, o);
    }
    if (lane == 0) { rs[wid] = s; rc[wid] = c; }
    __syncthreads();
    if (tid == 0) {
        float S = 0.f, Cc = 0.f;
        for (int w = 0; w < 8; w++) { S += rs[w]; Cc += rc[w]; }
        out[0] = -(S / Cc);
    }
}

// ---------------------------------------------------------------------------
extern "C" void kernel_launch(void* const* d_in, const int* in_sizes, int n_in,
                              void* d_out, int out_size) {
    const float* feat  = (const float*)d_in[0];
    const float* score = (const float*)d_in[1];
    const float* hm    = (const float*)d_in[2];
    float* out = (float*)d_out;

    // Output layout: [ -loss (1 float), pseudo_hm (16*80*128*128 floats) ]
    init_kernel<<<(BS * NC + 255) / 256, 256>>>();
    hm_kernel<<<BS * (HW / 4) / 256, 256>>>(hm);
    score_kernel<<<BS * 16, 256>>>(score, out, out_size);  // also zeroes out
    cand_kernel<<<BS, 1024>>>();
    gather_kernel<<<(BS * NKEY * 32 + 255) / 256, 256>>>(feat, out);
    loss_kernel<<<BS * 10, 256>>>();
    final_kernel<<<1, 256>>>(out);
}

// round 11
// speedup vs baseline: 1.1822x; 1.0200x over previous
#include <cuda_runtime.h>
#include <cuda_bf16.h>
#include <cstdint>
#include <math.h>

// Problem constants
constexpr int BS = 16, C = 64, H = 128, W = 128;
constexpr int HW = H * W;           // 16384
constexpr int NC = 80;
constexpr int TOPK = 128;
constexpr int NKEY = TOPK + NC;     // 208
constexpr int CAP = 4096;           // candidate buffer per batch
constexpr float CAND_T = 0.999f;    // prefilter threshold

// Scratch (device globals; no allocation allowed)
__device__ int                g_peak[BS * NC];
__device__ float              g_cmask[BS * NC];
__device__ float              g_hmfree[BS * HW];
__device__ float              g_maxval[BS * HW];
__device__ int                g_argcls[BS * HW];
__device__ int                g_ccount[BS];
__device__ unsigned long long g_cand[BS * CAP];
__device__ int                g_cand_cls[BS * CAP];
__device__ int                g_topk_idx[BS * TOPK];
__device__ float              g_topk_val[BS * TOPK];
__device__ int                g_topk_cls[BS * TOPK];
__device__ float              g_q[BS * NC * C];
__device__ float              g_ktop[BS * TOPK * C];
__device__ float              g_contrib[BS * NC];

// ---------------------------------------------------------------------------
__global__ void init_kernel() {
    int t = blockIdx.x * blockDim.x + threadIdx.x;
    if (t < BS * NC) { g_peak[t] = -1; g_cmask[t] = 0.f; }
    if (t < BS) g_ccount[t] = 0;
}

// ---------------------------------------------------------------------------
// Scan hm: find peak position per (b,c), class_mask, and per-pixel hm_free.
// Thread handles 4 consecutive pixels (float4); 8-deep prefetch for MLP.
__global__ void hm_kernel(const float* __restrict__ hm) {
    int t  = blockIdx.x * blockDim.x + threadIdx.x;
    int b  = t >> 12;
    int p4 = (t & 4095) << 2;
    const float* base = hm + (size_t)b * NC * HW + p4;
    float f0 = 1.f, f1 = 1.f, f2 = 1.f, f3 = 1.f;
#pragma unroll
    for (int cc = 0; cc < NC; cc += 8) {
        float4 r[8];
#pragma unroll
        for (int j = 0; j < 8; j++)
            r[j] = *reinterpret_cast<const float4*>(base + (cc + j) * HW);
#pragma unroll
        for (int j = 0; j < 8; j++) {
            int c = cc + j;
            if (r[j].x == 1.f) { f0 = 0.f; g_peak[b*NC+c] = p4;     g_cmask[b*NC+c] = 1.f; }
            if (r[j].y == 1.f) { f1 = 0.f; g_peak[b*NC+c] = p4 + 1; g_cmask[b*NC+c] = 1.f; }
            if (r[j].z == 1.f) { f2 = 0.f; g_peak[b*NC+c] = p4 + 2; g_cmask[b*NC+c] = 1.f; }
            if (r[j].w == 1.f) { f3 = 0.f; g_peak[b*NC+c] = p4 + 3; g_cmask[b*NC+c] = 1.f; }
        }
    }
    *reinterpret_cast<float4*>(&g_hmfree[b * HW + p4]) = make_float4(f0, f1, f2, f3);
}

// ---------------------------------------------------------------------------
// Masked per-pixel max/argmax over classes (first-max semantics), PLUS:
//  - candidate prefilter (maxval >= CAND_T -> packed candidate list)
//  - zeroing of the output buffer (replaces the separate memset pass)
__device__ __forceinline__ void add_candidate(int b, float m, int idx, int cls) {
    if (m >= CAND_T) {
        int pos = atomicAdd(&g_ccount[b], 1);
        if (pos < CAP) {
            unsigned vb = __float_as_uint(m);
            g_cand[b * CAP + pos] =
                ((unsigned long long)vb << 14) | (unsigned)(16383 - idx);
            g_cand_cls[b * CAP + pos] = cls;
        }
    }
}

__global__ void score_kernel(const float* __restrict__ score,
                             float* __restrict__ out, int out_size) {
    __shared__ float scm[NC];
    int b  = blockIdx.x >> 4;
    int p4 = ((((blockIdx.x & 15) << 8) + threadIdx.x)) << 2;
    if (threadIdx.x < NC) scm[threadIdx.x] = g_cmask[b * NC + threadIdx.x];
    __syncthreads();
    float4 hf = *reinterpret_cast<const float4*>(&g_hmfree[b * HW + p4]);
    const float* base = score + (size_t)b * NC * HW + p4;
    float m0 = 0.f, m1 = 0.f, m2 = 0.f, m3 = 0.f;
    int   c0 = 0,   c1 = 0,   c2 = 0,   c3 = 0;
#pragma unroll
    for (int cc = 0; cc < NC; cc += 8) {
        float4 r[8];
#pragma unroll
        for (int j = 0; j < 8; j++)
            r[j] = *reinterpret_cast<const float4*>(base + (cc + j) * HW);
#pragma unroll
        for (int j = 0; j < 8; j++) {
            int c = cc + j;
            float cm = scm[c];
            float s0 = r[j].x * cm * hf.x; if (s0 > m0) { m0 = s0; c0 = c; }
            float s1 = r[j].y * cm * hf.y; if (s1 > m1) { m1 = s1; c1 = c; }
            float s2 = r[j].z * cm * hf.z; if (s2 > m2) { m2 = s2; c2 = c; }
            float s3 = r[j].w * cm * hf.w; if (s3 > m3) { m3 = s3; c3 = c; }
        }
    }
    *reinterpret_cast<float4*>(&g_maxval[b * HW + p4]) = make_float4(m0, m1, m2, m3);
    *reinterpret_cast<int4*>(&g_argcls[b * HW + p4])   = make_int4(c0, c1, c2, c3);

    add_candidate(b, m0, p4,     c0);
    add_candidate(b, m1, p4 + 1, c1);
    add_candidate(b, m2, p4 + 2, c2);
    add_candidate(b, m3, p4 + 3, c3);

    // Zero the output buffer (grid-stride float4 across all 256 blocks).
    int   gtid = blockIdx.x * 256 + threadIdx.x;
    int   n4   = out_size >> 2;
    float4* o4 = reinterpret_cast<float4*>(out);
    const float4 z4 = make_float4(0.f, 0.f, 0.f, 0.f);
    for (int i = gtid; i < n4; i += 256 * 256) o4[i] = z4;
    if (gtid == 0)
        for (int i = n4 << 2; i < out_size; i++) out[i] = 0.f;
}

// ---------------------------------------------------------------------------
// Exact top-128 from the candidate list: pairwise rank count over M packed
// (value, 16383-idx) keys in smem. Inner loop unrolled 8x over zero-padded
// array (0 never outranks a real key) for MLP; rank r < 128 -> slot r.
// Deterministic, order-independent, jax tie semantics (lower idx first).
// Fallback to full binary search if the prefilter under/overflowed.
__global__ void cand_kernel() {
    const int b = blockIdx.x;
    const int tid = threadIdx.x, lane = tid & 31, wid = tid >> 5;  // 32 warps
    __shared__ unsigned long long sp[CAP + 8];   // 32 KB + pad
    int M = g_ccount[b];

    if (M >= TOPK && M <= CAP) {
        int Mpad = (M + 7) & ~7;
        for (int i = tid; i < Mpad; i += 1024)
            sp[i] = (i < M) ? g_cand[b * CAP + i] : 0ULL;
        __syncthreads();
        for (int i = tid; i < M; i += 1024) {
            unsigned long long me = sp[i];
            int r = 0;
            for (int j = 0; j < Mpad; j += 8) {
                unsigned long long k0 = sp[j    ], k1 = sp[j + 1];
                unsigned long long k2 = sp[j + 2], k3 = sp[j + 3];
                unsigned long long k4 = sp[j + 4], k5 = sp[j + 5];
                unsigned long long k6 = sp[j + 6], k7 = sp[j + 7];
                r += (k0 > me) + (k1 > me) + (k2 > me) + (k3 > me)
                   + (k4 > me) + (k5 > me) + (k6 > me) + (k7 > me);
            }
            if (r < TOPK) {
                unsigned vb = (unsigned)(me >> 14);
                int idx = 16383 - (int)(me & 16383u);
                g_topk_val[b * TOPK + r] = __uint_as_float(vb);
                g_topk_idx[b * TOPK + r] = idx;
                g_topk_cls[b * TOPK + r] = g_cand_cls[b * CAP + i];
            }
        }
        return;
    }

    // ---- Fallback: exact binary search on float bits over all 16384 ----
    const unsigned* mv = reinterpret_cast<const unsigned*>(g_maxval) + b * HW;
    unsigned v[16];
#pragma unroll
    for (int i = 0; i < 16; i++) v[i] = mv[i * 1024 + tid];

    __shared__ int s_warp[32];
    __shared__ int s_tot;

    auto blockCount = [&](unsigned thr, bool strict) -> int {
        __syncthreads();
        int c = 0;
#pragma unroll
        for (int i = 0; i < 16; i++) c += strict ? (v[i] > thr) : (v[i] >= thr);
        for (int o = 16; o; o >>= 1) c += __shfl_xor_sync(0xffffffffu, c, o);
        if (lane == 0) s_warp[wid] = c;
        __syncthreads();
        if (tid < 32) {
            int t2 = s_warp[tid];
            for (int o = 16; o; o >>= 1) t2 += __shfl_xor_sync(0xffffffffu, t2, o);
            if (tid == 0) s_tot = t2;
        }
        __syncthreads();
        return s_tot;
    };

    auto blockScanExcl = [&](int x) -> int {
        __syncthreads();
        int incl = x;
        for (int o = 1; o < 32; o <<= 1) {
            int t2 = __shfl_up_sync(0xffffffffu, incl, o);
            if (lane >= o) incl += t2;
        }
        if (lane == 31) s_warp[wid] = incl;
        __syncthreads();
        if (tid < 32) {
            int t2 = s_warp[tid];
            int inc2 = t2;
            for (int o = 1; o < 32; o <<= 1) {
                int u = __shfl_up_sync(0xffffffffu, inc2, o);
                if (tid >= o) inc2 += u;
            }
            s_warp[tid] = inc2 - t2;
        }
        __syncthreads();
        return s_warp[wid] + incl - x;
    };

    unsigned lo = 0, hi = 0x3F800000u;
    while (lo < hi) {
        unsigned mid = lo + ((hi - lo + 1) >> 1);
        int c = blockCount(mid, false);
        if (c >= TOPK) lo = mid; else hi = mid - 1;
    }
    unsigned V = lo;
    int G  = blockCount(V, true);
    int En = TOPK - G;

    int cgt = 0;
#pragma unroll
    for (int i = 0; i < 16; i++) cgt += (v[i] > V);
    int slot = blockScanExcl(cgt);
#pragma unroll
    for (int i = 0; i < 16; i++) {
        if (v[i] > V) {
            int idx = i * 1024 + tid;
            g_topk_val[b * TOPK + slot] = __uint_as_float(v[i]);
            g_topk_idx[b * TOPK + slot] = idx;
            g_topk_cls[b * TOPK + slot] = g_argcls[b * HW + idx];
            slot++;
        }
    }
    int ceq = 0;
#pragma unroll
    for (int i = 0; i < 16; i++) ceq += (v[i] == V);
    int r = blockScanExcl(ceq);
#pragma unroll
    for (int i = 0; i < 16; i++) {
        if (v[i] == V) {
            if (r < En) {
                int idx = i * 1024 + tid;
                int s2 = G + r;
                g_topk_val[b * TOPK + s2] = __uint_as_float(v[i]);
                g_topk_idx[b * TOPK + s2] = idx;
                g_topk_cls[b * TOPK + s2] = g_argcls[b * HW + idx];
            }
            r++;
        }
    }
}

// ---------------------------------------------------------------------------
// Gather + L2-normalize feat at peaks (-> q, == k0) and topk pixels (-> ktop).
// One warp per slot; lane handles channels lane and lane+32.
// Also fuses the pseudo_hm scatter (lane 0 of topk slots writes 0.9).
__global__ void gather_kernel(const float* __restrict__ feat, float* __restrict__ out) {
    int gw   = (blockIdx.x * blockDim.x + threadIdx.x) >> 5;
    int lane = threadIdx.x & 31;
    if (gw >= BS * NKEY) return;
    int b = gw / NKEY, s = gw % NKEY;
    float* dst;
    int p;
    if (s < NC) {
        p   = g_peak[b * NC + s];
        dst = g_q + (b * NC + s) * C;
        if (p < 0) { dst[lane] = 0.f; dst[lane + 32] = 0.f; return; }
    } else {
        int j = s - NC;
        p   = g_topk_idx[b * TOPK + j];
        dst = g_ktop + (b * TOPK + j) * C;
        if (lane == 0 && g_topk_val[b * TOPK + j] > 0.f) {
            out[1 + ((size_t)(b * NC + g_topk_cls[b * TOPK + j])) * HW + p] = 0.9f;
        }
    }
    const float* fp = feat + (size_t)b * C * HW + p;
    float a  = fp[(size_t)lane * HW];
    float b2 = fp[(size_t)(lane + 32) * HW];
    float ss = a * a + b2 * b2;
#pragma unroll
    for (int o = 16; o; o >>= 1) ss += __shfl_xor_sync(0xffffffffu, ss, o);
    float inv = 1.f / fmaxf(sqrtf(ss), 1e-12f);
    dst[lane]      = a  * inv;
    dst[lane + 32] = b2 * inv;
}

// ---------------------------------------------------------------------------
// Contrastive loss. Block = (batch, group of 8 classes). Keys staged in SMEM
// in two chunks (128 ktop rows, then 80 q rows == k0) so static SMEM < 48KB.
// log(sim_j / sim_sum) = d_j/tau - log(sim_sum).
__global__ void loss_kernel() {
    __shared__ float ks[TOPK * C];      // 32 KB (reused for both chunks)
    __shared__ float qs[8 * C];         // 2 KB
    __shared__ float r_s[8], r_d[8], r_n[8];
    __shared__ float acc_s[8], acc_d[8], acc_n[8];
    int b   = blockIdx.x / 10;
    int ng  = blockIdx.x % 10;          // classes [ng*8, ng*8+8)
    int tid = threadIdx.x, lane = tid & 31, wid = tid >> 5;

    const float* qb = g_q + b * NC * C;
    for (int i = tid; i < 8 * C; i += 256) qs[i] = qb[ng * 8 * C + i];

    // ---- chunk A: 128 topk keys ----
    const float* kt = g_ktop + b * TOPK * C;
    for (int i = tid; i < TOPK * C; i += 256) ks[i] = kt[i];
    float mallA = 0.f, kvalA = 0.f; int kclsA = -1;
    if (tid < TOPK) {
        kvalA = g_topk_val[b * TOPK + tid];
        mallA = (kvalA > 0.f) ? 1.f : 0.f;
        kclsA = g_topk_cls[b * TOPK + tid];
    }
    __syncthreads();
    for (int nl = 0; nl < 8; nl++) {
        int n = ng * 8 + nl;
        float ssum = 0.f, dsum = 0.f, num = 0.f;
        if (tid < TOPK) {
            float d = 0.f;
            const float* kr = ks + tid * C;
            const float* qr = qs + nl * C;
#pragma unroll
            for (int c = 0; c < C; c++) {
                int cc = (c + tid) & (C - 1);
                d += kr[cc] * qr[cc];
            }
            float dt = d / 0.07f;
            float mm = (kclsA == n && kvalA > 0.f) ? 1.f : 0.f;
            ssum = expf(dt) * mallA;
            dsum = dt * mm;
            num  = mm;
        }
        for (int o = 16; o; o >>= 1) {
            ssum += __shfl_xor_sync(0xffffffffu, ssum, o);
            dsum += __shfl_xor_sync(0xffffffffu, dsum, o);
            num  += __shfl_xor_sync(0xffffffffu, num,  o);
        }
        if (lane == 0) { r_s[wid] = ssum; r_d[wid] = dsum; r_n[wid] = num; }
        __syncthreads();
        if (tid == 0) {
            float S = 0.f, D = 0.f, N = 0.f;
            for (int w = 0; w < 8; w++) { S += r_s[w]; D += r_d[w]; N += r_n[w]; }
            acc_s[nl] = S; acc_d[nl] = D; acc_n[nl] = N;
        }
        __syncthreads();
    }

    // ---- chunk B: 80 k0 keys (== q rows) ----
    for (int i = tid; i < NC * C; i += 256) ks[i] = qb[i];
    float mallB = 0.f;
    if (tid < NC) mallB = g_cmask[b * NC + tid];
    __syncthreads();
    for (int nl = 0; nl < 8; nl++) {
        int n = ng * 8 + nl;
        float cm = g_cmask[b * NC + n];
        float ssum = 0.f, dsum = 0.f, num = 0.f;
        if (tid < NC) {
            float d = 0.f;
            const float* kr = ks + tid * C;
            const float* qr = qs + nl * C;
#pragma unroll
            for (int c = 0; c < C; c++) {
                int cc = (c + tid) & (C - 1);
                d += kr[cc] * qr[cc];
            }
            float dt = d / 0.07f;
            float mm = (tid == n) ? cm : 0.f;   // k0_mask diagonal
            ssum = expf(dt) * mallB;
            dsum = dt * mm;
            num  = mm;
        }
        for (int o = 16; o; o >>= 1) {
            ssum += __shfl_xor_sync(0xffffffffu, ssum, o);
            dsum += __shfl_xor_sync(0xffffffffu, dsum, o);
            num  += __shfl_xor_sync(0xffffffffu, num,  o);
        }
        if (lane == 0) { r_s[wid] = ssum; r_d[wid] = dsum; r_n[wid] = num; }
        __syncthreads();
        if (tid == 0) {
            float S = acc_s[nl], D = acc_d[nl], N = acc_n[nl];
            for (int w = 0; w < 8; w++) { S += r_s[w]; D += r_d[w]; N += r_n[w]; }
            float outv = 0.f;
            if (cm != 0.f) outv = (D - N * logf(S)) / N;  // N >= 1 (diagonal)
            g_contrib[b * NC + n] = outv;
        }
        __syncthreads();
    }
}

// ---------------------------------------------------------------------------
__global__ void final_kernel(float* __restrict__ out) {
    __shared__ float rs[8], rc[8];
    int tid = threadIdx.x, lane = tid & 31, wid = tid >> 5;
    float s = 0.f, c = 0.f;
    for (int i = tid; i < BS * NC; i += 256) { s += g_contrib[i]; c += g_cmask[i]; }
    for (int o = 16; o; o >>= 1) {
        s += __shfl_xor_sync(0xffffffffu, s, o);
        c += __shfl_xor_sync(0xffffffffu, c, o);
    }
    if (lane == 0) { rs[wid] = s; rc[wid] = c; }
    __syncthreads();
    if (tid == 0) {
        float S = 0.f, Cc = 0.f;
        for (int w = 0; w < 8; w++) { S += rs[w]; Cc += rc[w]; }
        out[0] = -(S / Cc);
    }
}

// ---------------------------------------------------------------------------
extern "C" void kernel_launch(void* const* d_in, const int* in_sizes, int n_in,
                              void* d_out, int out_size) {
    const float* feat  = (const float*)d_in[0];
    const float* score = (const float*)d_in[1];
    const float* hm    = (const float*)d_in[2];
    float* out = (float*)d_out;

    // Output layout: [ -loss (1 float), pseudo_hm (16*80*128*128 floats) ]
    init_kernel<<<(BS * NC + 255) / 256, 256>>>();
    hm_kernel<<<BS * (HW / 4) / 256, 256>>>(hm);
    score_kernel<<<BS * 16, 256>>>(score, out, out_size);  // also zeroes out
    cand_kernel<<<BS, 1024>>>();
    gather_kernel<<<(BS * NKEY * 32 + 255) / 256, 256>>>(feat, out);
    loss_kernel<<<BS * 10, 256>>>();
    final_kernel<<<1, 256>>>(out);
}

// round 13
// speedup vs baseline: 1.2573x; 1.0635x over previous
#include <cuda_runtime.h>
#include <cuda_bf16.h>
#include <cstdint>
#include <math.h>

// Problem constants
constexpr int BS = 16, C = 64, H = 128, W = 128;
constexpr int HW = H * W;           // 16384
constexpr int NC = 80;
constexpr int TOPK = 128;
constexpr int NKEY = TOPK + NC;     // 208
constexpr int CAP = 4096;           // candidate buffer per batch
constexpr int SLICES = 8;           // rank-kernel blocks per batch
constexpr float CAND_T = 0.999f;    // prefilter threshold

// Scratch (device globals; no allocation allowed)
__device__ int                g_peak[BS * NC];
__device__ float              g_cmask[BS * NC];
__device__ float              g_hmfree[BS * HW];
__device__ float              g_maxval[BS * HW];
__device__ int                g_argcls[BS * HW];
__device__ int                g_ccount[BS];
__device__ unsigned long long g_cand[BS * CAP];
__device__ int                g_cand_cls[BS * CAP];
__device__ int                g_topk_idx[BS * TOPK];
__device__ float              g_topk_val[BS * TOPK];
__device__ int                g_topk_cls[BS * TOPK];
__device__ float              g_q[BS * NC * C];
__device__ float              g_ktop[BS * TOPK * C];
__device__ float              g_contrib[BS * NC];

// ---------------------------------------------------------------------------
__global__ void init_kernel() {
    int t = blockIdx.x * blockDim.x + threadIdx.x;
    if (t < BS * NC) { g_peak[t] = -1; g_cmask[t] = 0.f; }
    if (t < BS) g_ccount[t] = 0;
}

// ---------------------------------------------------------------------------
// Scan hm: find peak position per (b,c), class_mask, and per-pixel hm_free.
// Thread handles 4 consecutive pixels (float4); 8-deep prefetch for MLP.
__global__ void hm_kernel(const float* __restrict__ hm) {
    int t  = blockIdx.x * blockDim.x + threadIdx.x;
    int b  = t >> 12;
    int p4 = (t & 4095) << 2;
    const float* base = hm + (size_t)b * NC * HW + p4;
    float f0 = 1.f, f1 = 1.f, f2 = 1.f, f3 = 1.f;
#pragma unroll
    for (int cc = 0; cc < NC; cc += 8) {
        float4 r[8];
#pragma unroll
        for (int j = 0; j < 8; j++)
            r[j] = *reinterpret_cast<const float4*>(base + (cc + j) * HW);
#pragma unroll
        for (int j = 0; j < 8; j++) {
            int c = cc + j;
            if (r[j].x == 1.f) { f0 = 0.f; g_peak[b*NC+c] = p4;     g_cmask[b*NC+c] = 1.f; }
            if (r[j].y == 1.f) { f1 = 0.f; g_peak[b*NC+c] = p4 + 1; g_cmask[b*NC+c] = 1.f; }
            if (r[j].z == 1.f) { f2 = 0.f; g_peak[b*NC+c] = p4 + 2; g_cmask[b*NC+c] = 1.f; }
            if (r[j].w == 1.f) { f3 = 0.f; g_peak[b*NC+c] = p4 + 3; g_cmask[b*NC+c] = 1.f; }
        }
    }
    *reinterpret_cast<float4*>(&g_hmfree[b * HW + p4]) = make_float4(f0, f1, f2, f3);
}

// ---------------------------------------------------------------------------
// Masked per-pixel max/argmax over classes (first-max semantics), PLUS:
//  - candidate prefilter (maxval >= CAND_T -> packed candidate list)
//  - zeroing of the output buffer (replaces the separate memset pass)
__device__ __forceinline__ void add_candidate(int b, float m, int idx, int cls) {
    if (m >= CAND_T) {
        int pos = atomicAdd(&g_ccount[b], 1);
        if (pos < CAP) {
            unsigned vb = __float_as_uint(m);
            g_cand[b * CAP + pos] =
                ((unsigned long long)vb << 14) | (unsigned)(16383 - idx);
            g_cand_cls[b * CAP + pos] = cls;
        }
    }
}

__global__ void score_kernel(const float* __restrict__ score,
                             float* __restrict__ out, int out_size) {
    __shared__ float scm[NC];
    int b  = blockIdx.x >> 4;
    int p4 = ((((blockIdx.x & 15) << 8) + threadIdx.x)) << 2;
    if (threadIdx.x < NC) scm[threadIdx.x] = g_cmask[b * NC + threadIdx.x];
    __syncthreads();
    float4 hf = *reinterpret_cast<const float4*>(&g_hmfree[b * HW + p4]);
    const float* base = score + (size_t)b * NC * HW + p4;
    float m0 = 0.f, m1 = 0.f, m2 = 0.f, m3 = 0.f;
    int   c0 = 0,   c1 = 0,   c2 = 0,   c3 = 0;
#pragma unroll
    for (int cc = 0; cc < NC; cc += 8) {
        float4 r[8];
#pragma unroll
        for (int j = 0; j < 8; j++)
            r[j] = *reinterpret_cast<const float4*>(base + (cc + j) * HW);
#pragma unroll
        for (int j = 0; j < 8; j++) {
            int c = cc + j;
            float cm = scm[c];
            float s0 = r[j].x * cm * hf.x; if (s0 > m0) { m0 = s0; c0 = c; }
            float s1 = r[j].y * cm * hf.y; if (s1 > m1) { m1 = s1; c1 = c; }
            float s2 = r[j].z * cm * hf.z; if (s2 > m2) { m2 = s2; c2 = c; }
            float s3 = r[j].w * cm * hf.w; if (s3 > m3) { m3 = s3; c3 = c; }
        }
    }
    *reinterpret_cast<float4*>(&g_maxval[b * HW + p4]) = make_float4(m0, m1, m2, m3);
    *reinterpret_cast<int4*>(&g_argcls[b * HW + p4])   = make_int4(c0, c1, c2, c3);

    add_candidate(b, m0, p4,     c0);
    add_candidate(b, m1, p4 + 1, c1);
    add_candidate(b, m2, p4 + 2, c2);
    add_candidate(b, m3, p4 + 3, c3);

    // Zero the output buffer (grid-stride float4 across all 256 blocks).
    int   gtid = blockIdx.x * 256 + threadIdx.x;
    int   n4   = out_size >> 2;
    float4* o4 = reinterpret_cast<float4*>(out);
    const float4 z4 = make_float4(0.f, 0.f, 0.f, 0.f);
    for (int i = gtid; i < n4; i += 256 * 256) o4[i] = z4;
    if (gtid == 0)
        for (int i = n4 << 2; i < out_size; i++) out[i] = 0.f;
}

// ---------------------------------------------------------------------------
// Exact top-128 from the candidate list, spread over SLICES blocks per batch.
// Each block loads all M packed keys (~5 KB) to smem and ranks 1/SLICES of
// the candidates by pairwise comparison (8x unrolled over zero-padded keys;
// 0 never outranks a real key). rank r < 128 -> slot r. Deterministic,
// order-independent, jax tie semantics (lower pixel idx wins on equal value).
__global__ void rank_kernel() {
    const int b  = blockIdx.x / SLICES;
    const int sl = blockIdx.x % SLICES;
    const int M  = g_ccount[b];
    if (M < TOPK || M > CAP) return;            // fallback kernel handles it

    __shared__ unsigned long long sp[CAP + 8];
    const int Mpad = (M + 7) & ~7;
    for (int i = threadIdx.x; i < Mpad; i += 256)
        sp[i] = (i < M) ? g_cand[b * CAP + i] : 0ULL;
    __syncthreads();

    const int per = (M + SLICES - 1) / SLICES;
    const int ilo = sl * per;
    const int ihi = (ilo + per < M) ? ilo + per : M;
    for (int i = ilo + threadIdx.x; i < ihi; i += 256) {
        unsigned long long me = sp[i];
        int r = 0;
        for (int j = 0; j < Mpad; j += 8) {
            unsigned long long k0 = sp[j    ], k1 = sp[j + 1];
            unsigned long long k2 = sp[j + 2], k3 = sp[j + 3];
            unsigned long long k4 = sp[j + 4], k5 = sp[j + 5];
            unsigned long long k6 = sp[j + 6], k7 = sp[j + 7];
            r += (k0 > me) + (k1 > me) + (k2 > me) + (k3 > me)
               + (k4 > me) + (k5 > me) + (k6 > me) + (k7 > me);
        }
        if (r < TOPK) {
            unsigned vb = (unsigned)(me >> 14);
            int idx = 16383 - (int)(me & 16383u);
            g_topk_val[b * TOPK + r] = __uint_as_float(vb);
            g_topk_idx[b * TOPK + r] = idx;
            g_topk_cls[b * TOPK + r] = g_cand_cls[b * CAP + i];
        }
    }
}

// ---------------------------------------------------------------------------
// Fallback only: exact binary search on float bits over all 16384 values.
// Early-exits when the prefilter succeeded (the expected case).
__global__ void cand_fallback_kernel() {
    const int b = blockIdx.x;
    const int M = g_ccount[b];
    if (M >= TOPK && M <= CAP) return;          // rank_kernel handled it

    const int tid = threadIdx.x, lane = tid & 31, wid = tid >> 5;
    const unsigned* mv = reinterpret_cast<const unsigned*>(g_maxval) + b * HW;
    unsigned v[16];
#pragma unroll
    for (int i = 0; i < 16; i++) v[i] = mv[i * 1024 + tid];

    __shared__ int s_warp[32];
    __shared__ int s_tot;

    auto blockCount = [&](unsigned thr, bool strict) -> int {
        __syncthreads();
        int c = 0;
#pragma unroll
        for (int i = 0; i < 16; i++) c += strict ? (v[i] > thr) : (v[i] >= thr);
        for (int o = 16; o; o >>= 1) c += __shfl_xor_sync(0xffffffffu, c, o);
        if (lane == 0) s_warp[wid] = c;
        __syncthreads();
        if (tid < 32) {
            int t2 = s_warp[tid];
            for (int o = 16; o; o >>= 1) t2 += __shfl_xor_sync(0xffffffffu, t2, o);
            if (tid == 0) s_tot = t2;
        }
        __syncthreads();
        return s_tot;
    };

    auto blockScanExcl = [&](int x) -> int {
        __syncthreads();
        int incl = x;
        for (int o = 1; o < 32; o <<= 1) {
            int t2 = __shfl_up_sync(0xffffffffu, incl, o);
            if (lane >= o) incl += t2;
        }
        if (lane == 31) s_warp[wid] = incl;
        __syncthreads();
        if (tid < 32) {
            int t2 = s_warp[tid];
            int inc2 = t2;
            for (int o = 1; o < 32; o <<= 1) {
                int u = __shfl_up_sync(0xffffffffu, inc2, o);
                if (tid >= o) inc2 += u;
            }
            s_warp[tid] = inc2 - t2;
        }
        __syncthreads();
        return s_warp[wid] + incl - x;
    };

    unsigned lo = 0, hi = 0x3F800000u;
    while (lo < hi) {
        unsigned mid = lo + ((hi - lo + 1) >> 1);
        int c = blockCount(mid, false);
        if (c >= TOPK) lo = mid; else hi = mid - 1;
    }
    unsigned V = lo;
    int G  = blockCount(V, true);
    int En = TOPK - G;

    int cgt = 0;
#pragma unroll
    for (int i = 0; i < 16; i++) cgt += (v[i] > V);
    int slot = blockScanExcl(cgt);
#pragma unroll
    for (int i = 0; i < 16; i++) {
        if (v[i] > V) {
            int idx = i * 1024 + tid;
            g_topk_val[b * TOPK + slot] = __uint_as_float(v[i]);
            g_topk_idx[b * TOPK + slot] = idx;
            g_topk_cls[b * TOPK + slot] = g_argcls[b * HW + idx];
            slot++;
        }
    }
    int ceq = 0;
#pragma unroll
    for (int i = 0; i < 16; i++) ceq += (v[i] == V);
    int r = blockScanExcl(ceq);
#pragma unroll
    for (int i = 0; i < 16; i++) {
        if (v[i] == V) {
            if (r < En) {
                int idx = i * 1024 + tid;
                int s2 = G + r;
                g_topk_val[b * TOPK + s2] = __uint_as_float(v[i]);
                g_topk_idx[b * TOPK + s2] = idx;
                g_topk_cls[b * TOPK + s2] = g_argcls[b * HW + idx];
            }
            r++;
        }
    }
}

// ---------------------------------------------------------------------------
// Gather + L2-normalize feat at peaks (-> q, == k0) and topk pixels (-> ktop).
// One warp per slot; lane handles channels lane and lane+32.
// Also fuses the pseudo_hm scatter (lane 0 of topk slots writes 0.9).
__global__ void gather_kernel(const float* __restrict__ feat, float* __restrict__ out) {
    int gw   = (blockIdx.x * blockDim.x + threadIdx.x) >> 5;
    int lane = threadIdx.x & 31;
    if (gw >= BS * NKEY) return;
    int b = gw / NKEY, s = gw % NKEY;
    float* dst;
    int p;
    if (s < NC) {
        p   = g_peak[b * NC + s];
        dst = g_q + (b * NC + s) * C;
        if (p < 0) { dst[lane] = 0.f; dst[lane + 32] = 0.f; return; }
    } else {
        int j = s - NC;
        p   = g_topk_idx[b * TOPK + j];
        dst = g_ktop + (b * TOPK + j) * C;
        if (lane == 0 && g_topk_val[b * TOPK + j] > 0.f) {
            out[1 + ((size_t)(b * NC + g_topk_cls[b * TOPK + j])) * HW + p] = 0.9f;
        }
    }
    const float* fp = feat + (size_t)b * C * HW + p;
    float a  = fp[(size_t)lane * HW];
    float b2 = fp[(size_t)(lane + 32) * HW];
    float ss = a * a + b2 * b2;
#pragma unroll
    for (int o = 16; o; o >>= 1) ss += __shfl_xor_sync(0xffffffffu, ss, o);
    float inv = 1.f / fmaxf(sqrtf(ss), 1e-12f);
    dst[lane]      = a  * inv;
    dst[lane + 32] = b2 * inv;
}

// ---------------------------------------------------------------------------
// Contrastive loss. Block = (batch, group of 8 classes). Keys staged in SMEM
// in two chunks (128 ktop rows, then 80 q rows == k0) so static SMEM < 48KB.
// log(sim_j / sim_sum) = d_j/tau - log(sim_sum).
__global__ void loss_kernel() {
    __shared__ float ks[TOPK * C];      // 32 KB (reused for both chunks)
    __shared__ float qs[8 * C];         // 2 KB
    __shared__ float r_s[8], r_d[8], r_n[8];
    __shared__ float acc_s[8], acc_d[8], acc_n[8];
    int b   = blockIdx.x / 10;
    int ng  = blockIdx.x % 10;          // classes [ng*8, ng*8+8)
    int tid = threadIdx.x, lane = tid & 31, wid = tid >> 5;

    const float* qb = g_q + b * NC * C;
    for (int i = tid; i < 8 * C; i += 256) qs[i] = qb[ng * 8 * C + i];

    // ---- chunk A: 128 topk keys ----
    const float* kt = g_ktop + b * TOPK * C;
    for (int i = tid; i < TOPK * C; i += 256) ks[i] = kt[i];
    float mallA = 0.f, kvalA = 0.f; int kclsA = -1;
    if (tid < TOPK) {
        kvalA = g_topk_val[b * TOPK + tid];
        mallA = (kvalA > 0.f) ? 1.f : 0.f;
        kclsA = g_topk_cls[b * TOPK + tid];
    }
    __syncthreads();
    for (int nl = 0; nl < 8; nl++) {
        int n = ng * 8 + nl;
        float ssum = 0.f, dsum = 0.f, num = 0.f;
        if (tid < TOPK) {
            float d = 0.f;
            const float* kr = ks + tid * C;
            const float* qr = qs + nl * C;
#pragma unroll
            for (int c = 0; c < C; c++) {
                int cc = (c + tid) & (C - 1);
                d += kr[cc] * qr[cc];
            }
            float dt = d / 0.07f;
            float mm = (kclsA == n && kvalA > 0.f) ? 1.f : 0.f;
            ssum = expf(dt) * mallA;
            dsum = dt * mm;
            num  = mm;
        }
        for (int o = 16; o; o >>= 1) {
            ssum += __shfl_xor_sync(0xffffffffu, ssum, o);
            dsum += __shfl_xor_sync(0xffffffffu, dsum, o);
            num  += __shfl_xor_sync(0xffffffffu, num,  o);
        }
        if (lane == 0) { r_s[wid] = ssum; r_d[wid] = dsum; r_n[wid] = num; }
        __syncthreads();
        if (tid == 0) {
            float S = 0.f, D = 0.f, N = 0.f;
            for (int w = 0; w < 8; w++) { S += r_s[w]; D += r_d[w]; N += r_n[w]; }
            acc_s[nl] = S; acc_d[nl] = D; acc_n[nl] = N;
        }
        __syncthreads();
    }

    // ---- chunk B: 80 k0 keys (== q rows) ----
    for (int i = tid; i < NC * C; i += 256) ks[i] = qb[i];
    float mallB = 0.f;
    if (tid < NC) mallB = g_cmask[b * NC + tid];
    __syncthreads();
    for (int nl = 0; nl < 8; nl++) {
        int n = ng * 8 + nl;
        float cm = g_cmask[b * NC + n];
        float ssum = 0.f, dsum = 0.f, num = 0.f;
        if (tid < NC) {
            float d = 0.f;
            const float* kr = ks + tid * C;
            const float* qr = qs + nl * C;
#pragma unroll
            for (int c = 0; c < C; c++) {
                int cc = (c + tid) & (C - 1);
                d += kr[cc] * qr[cc];
            }
            float dt = d / 0.07f;
            float mm = (tid == n) ? cm : 0.f;   // k0_mask diagonal
            ssum = expf(dt) * mallB;
            dsum = dt * mm;
            num  = mm;
        }
        for (int o = 16; o; o >>= 1) {
            ssum += __shfl_xor_sync(0xffffffffu, ssum, o);
            dsum += __shfl_xor_sync(0xffffffffu, dsum, o);
            num  += __shfl_xor_sync(0xffffffffu, num,  o);
        }
        if (lane == 0) { r_s[wid] = ssum; r_d[wid] = dsum; r_n[wid] = num; }
        __syncthreads();
        if (tid == 0) {
            float S = acc_s[nl], D = acc_d[nl], N = acc_n[nl];
            for (int w = 0; w < 8; w++) { S += r_s[w]; D += r_d[w]; N += r_n[w]; }
            float outv = 0.f;
            if (cm != 0.f) outv = (D - N * logf(S)) / N;  // N >= 1 (diagonal)
            g_contrib[b * NC + n] = outv;
        }
        __syncthreads();
    }
}

// ---------------------------------------------------------------------------
__global__ void final_kernel(float* __restrict__ out) {
    __shared__ float rs[8], rc[8];
    int tid = threadIdx.x, lane = tid & 31, wid = tid >> 5;
    float s = 0.f, c = 0.f;
    for (int i = tid; i < BS * NC; i += 256) { s += g_contrib[i]; c += g_cmask[i]; }
    for (int o = 16; o; o >>= 1) {
        s += __shfl_xor_sync(0xffffffffu, s, o);
        c += __shfl_xor_sync(0xffffffffu, c, o);
    }
    if (lane == 0) { rs[wid] = s; rc[wid] = c; }
    __syncthreads();
    if (tid == 0) {
        float S = 0.f, Cc = 0.f;
        for (int w = 0; w < 8; w++) { S += rs[w]; Cc += rc[w]; }
        out[0] = -(S / Cc);
    }
}

// ---------------------------------------------------------------------------
extern "C" void kernel_launch(void* const* d_in, const int* in_sizes, int n_in,
                              void* d_out, int out_size) {
    const float* feat  = (const float*)d_in[0];
    const float* score = (const float*)d_in[1];
    const float* hm    = (const float*)d_in[2];
    float* out = (float*)d_out;

    // Output layout: [ -loss (1 float), pseudo_hm (16*80*128*128 floats) ]
    init_kernel<<<(BS * NC + 255) / 256, 256>>>();
    hm_kernel<<<BS * (HW / 4) / 256, 256>>>(hm);
    score_kernel<<<BS * 16, 256>>>(score, out, out_size);  // also zeroes out
    rank_kernel<<<BS * SLICES, 256>>>();
    cand_fallback_kernel<<<BS, 1024>>>();
    gather_kernel<<<(BS * NKEY * 32 + 255) / 256, 256>>>(feat, out);
    loss_kernel<<<BS * 10, 256>>>();
    final_kernel<<<1, 256>>>(out);
}

// round 14
// speedup vs baseline: 1.4600x; 1.1612x over previous
#include <cuda_runtime.h>
#include <cuda_bf16.h>
#include <cstdint>
#include <math.h>

// Problem constants
constexpr int BS = 16, C = 64, H = 128, W = 128;
constexpr int HW = H * W;           // 16384
constexpr int NC = 80;
constexpr int TOPK = 128;
constexpr int NKEY = TOPK + NC;     // 208
constexpr int CAP = 4096;           // candidate buffer per batch
constexpr int SLICES = 8;           // rank-kernel blocks per batch
constexpr float CAND_T = 0.999f;    // prefilter threshold

// Scratch (device globals; no allocation allowed)
__device__ int                g_peak[BS * NC];
__device__ float              g_cmask[BS * NC];
__device__ float              g_hmfree[BS * HW];
__device__ float              g_maxval[BS * HW];
__device__ int                g_argcls[BS * HW];
__device__ int                g_ccount[BS];
__device__ unsigned long long g_cand[BS * CAP];
__device__ int                g_cand_cls[BS * CAP];
__device__ int                g_topk_idx[BS * TOPK];
__device__ float              g_topk_val[BS * TOPK];
__device__ int                g_topk_cls[BS * TOPK];
__device__ float              g_q[BS * NC * C];
__device__ float              g_ktop[BS * TOPK * C];
__device__ float              g_loss_sum;
__device__ float              g_loss_cnt;
__device__ int                g_loss_done;

// ---------------------------------------------------------------------------
__global__ void init_kernel() {
    int t = blockIdx.x * blockDim.x + threadIdx.x;
    if (t < BS * NC) { g_peak[t] = -1; g_cmask[t] = 0.f; }
    if (t < BS) g_ccount[t] = 0;
    if (t == 0) { g_loss_sum = 0.f; g_loss_cnt = 0.f; g_loss_done = 0; }
}

// ---------------------------------------------------------------------------
// Scan hm: peaks, class_mask, hm_free. Also zeroes the FIRST half of the
// output buffer (other half is zeroed by score_kernel -> balanced traffic).
__global__ void hm_kernel(const float* __restrict__ hm,
                          float* __restrict__ out, int out_size) {
    int t  = blockIdx.x * blockDim.x + threadIdx.x;
    int b  = t >> 12;
    int p4 = (t & 4095) << 2;
    const float* base = hm + (size_t)b * NC * HW + p4;
    float f0 = 1.f, f1 = 1.f, f2 = 1.f, f3 = 1.f;
#pragma unroll
    for (int cc = 0; cc < NC; cc += 8) {
        float4 r[8];
#pragma unroll
        for (int j = 0; j < 8; j++)
            r[j] = *reinterpret_cast<const float4*>(base + (cc + j) * HW);
#pragma unroll
        for (int j = 0; j < 8; j++) {
            int c = cc + j;
            if (r[j].x == 1.f) { f0 = 0.f; g_peak[b*NC+c] = p4;     g_cmask[b*NC+c] = 1.f; }
            if (r[j].y == 1.f) { f1 = 0.f; g_peak[b*NC+c] = p4 + 1; g_cmask[b*NC+c] = 1.f; }
            if (r[j].z == 1.f) { f2 = 0.f; g_peak[b*NC+c] = p4 + 2; g_cmask[b*NC+c] = 1.f; }
            if (r[j].w == 1.f) { f3 = 0.f; g_peak[b*NC+c] = p4 + 3; g_cmask[b*NC+c] = 1.f; }
        }
    }
    *reinterpret_cast<float4*>(&g_hmfree[b * HW + p4]) = make_float4(f0, f1, f2, f3);

    // Zero first half of output (float4 grid-stride).
    int   n4  = out_size >> 2;
    int   n4h = n4 >> 1;
    float4* o4 = reinterpret_cast<float4*>(out);
    const float4 z4 = make_float4(0.f, 0.f, 0.f, 0.f);
    for (int i = t; i < n4h; i += 65536) o4[i] = z4;
}

// ---------------------------------------------------------------------------
// Masked per-pixel max/argmax over classes (first-max semantics), PLUS:
//  - candidate prefilter (maxval >= CAND_T -> packed candidate list)
//  - zeroing of the SECOND half of the output buffer
__device__ __forceinline__ void add_candidate(int b, float m, int idx, int cls) {
    if (m >= CAND_T) {
        int pos = atomicAdd(&g_ccount[b], 1);
        if (pos < CAP) {
            unsigned vb = __float_as_uint(m);
            g_cand[b * CAP + pos] =
                ((unsigned long long)vb << 14) | (unsigned)(16383 - idx);
            g_cand_cls[b * CAP + pos] = cls;
        }
    }
}

__global__ void score_kernel(const float* __restrict__ score,
                             float* __restrict__ out, int out_size) {
    __shared__ float scm[NC];
    int b  = blockIdx.x >> 4;
    int p4 = ((((blockIdx.x & 15) << 8) + threadIdx.x)) << 2;
    if (threadIdx.x < NC) scm[threadIdx.x] = g_cmask[b * NC + threadIdx.x];
    __syncthreads();
    float4 hf = *reinterpret_cast<const float4*>(&g_hmfree[b * HW + p4]);
    const float* base = score + (size_t)b * NC * HW + p4;
    float m0 = 0.f, m1 = 0.f, m2 = 0.f, m3 = 0.f;
    int   c0 = 0,   c1 = 0,   c2 = 0,   c3 = 0;
#pragma unroll
    for (int cc = 0; cc < NC; cc += 8) {
        float4 r[8];
#pragma unroll
        for (int j = 0; j < 8; j++)
            r[j] = *reinterpret_cast<const float4*>(base + (cc + j) * HW);
#pragma unroll
        for (int j = 0; j < 8; j++) {
            int c = cc + j;
            float cm = scm[c];
            float s0 = r[j].x * cm * hf.x; if (s0 > m0) { m0 = s0; c0 = c; }
            float s1 = r[j].y * cm * hf.y; if (s1 > m1) { m1 = s1; c1 = c; }
            float s2 = r[j].z * cm * hf.z; if (s2 > m2) { m2 = s2; c2 = c; }
            float s3 = r[j].w * cm * hf.w; if (s3 > m3) { m3 = s3; c3 = c; }
        }
    }
    *reinterpret_cast<float4*>(&g_maxval[b * HW + p4]) = make_float4(m0, m1, m2, m3);
    *reinterpret_cast<int4*>(&g_argcls[b * HW + p4])   = make_int4(c0, c1, c2, c3);

    add_candidate(b, m0, p4,     c0);
    add_candidate(b, m1, p4 + 1, c1);
    add_candidate(b, m2, p4 + 2, c2);
    add_candidate(b, m3, p4 + 3, c3);

    // Zero second half of output (float4 grid-stride) + tail.
    int   gtid = blockIdx.x * 256 + threadIdx.x;
    int   n4   = out_size >> 2;
    int   n4h  = n4 >> 1;
    float4* o4 = reinterpret_cast<float4*>(out);
    const float4 z4 = make_float4(0.f, 0.f, 0.f, 0.f);
    for (int i = n4h + gtid; i < n4; i += 65536) o4[i] = z4;
    if (gtid == 0)
        for (int i = n4 << 2; i < out_size; i++) out[i] = 0.f;
}

// ---------------------------------------------------------------------------
// Exact top-128 from the candidate list, spread over SLICES blocks per batch.
// Each block loads all M packed keys (~5 KB) to smem and ranks 1/SLICES of
// the candidates by pairwise comparison (8x unrolled over zero-padded keys;
// 0 never outranks a real key). rank r < 128 -> slot r. Deterministic,
// order-independent, jax tie semantics (lower pixel idx wins on equal value).
// If the prefilter under/overflowed (not expected), slice 0 runs an exact
// binary-search fallback over all 16384 values (global reads, cold path).
__global__ void rank_kernel() {
    const int b  = blockIdx.x / SLICES;
    const int sl = blockIdx.x % SLICES;
    const int M  = g_ccount[b];
    const int tid = threadIdx.x;

    __shared__ unsigned long long sp[CAP + 8];

    if (M >= TOPK && M <= CAP) {
        const int Mpad = (M + 7) & ~7;
        for (int i = tid; i < Mpad; i += 256)
            sp[i] = (i < M) ? g_cand[b * CAP + i] : 0ULL;
        __syncthreads();

        const int per = (M + SLICES - 1) / SLICES;
        const int ilo = sl * per;
        const int ihi = (ilo + per < M) ? ilo + per : M;
        for (int i = ilo + tid; i < ihi; i += 256) {
            unsigned long long me = sp[i];
            int r = 0;
            for (int j = 0; j < Mpad; j += 8) {
                unsigned long long k0 = sp[j    ], k1 = sp[j + 1];
                unsigned long long k2 = sp[j + 2], k3 = sp[j + 3];
                unsigned long long k4 = sp[j + 4], k5 = sp[j + 5];
                unsigned long long k6 = sp[j + 6], k7 = sp[j + 7];
                r += (k0 > me) + (k1 > me) + (k2 > me) + (k3 > me)
                   + (k4 > me) + (k5 > me) + (k6 > me) + (k7 > me);
            }
            if (r < TOPK) {
                unsigned vb = (unsigned)(me >> 14);
                int idx = 16383 - (int)(me & 16383u);
                g_topk_val[b * TOPK + r] = __uint_as_float(vb);
                g_topk_idx[b * TOPK + r] = idx;
                g_topk_cls[b * TOPK + r] = g_cand_cls[b * HW > 0 ? b * CAP + i : b * CAP + i];
            }
        }
        return;
    }

    // ---- Fallback (cold path): exact binary search, 256 threads, global reads.
    if (sl != 0) return;
    const int lane = tid & 31, wid = tid >> 5;   // 8 warps
    const unsigned* mv = reinterpret_cast<const unsigned*>(g_maxval) + b * HW;

    __shared__ int s_warp[8];
    __shared__ int s_tot;

    auto blockCount = [&](unsigned thr, bool strict) -> int {
        __syncthreads();
        int c = 0;
        for (int i = 0; i < 64; i++) {
            unsigned x = mv[i * 256 + tid];
            c += strict ? (x > thr) : (x >= thr);
        }
        for (int o = 16; o; o >>= 1) c += __shfl_xor_sync(0xffffffffu, c, o);
        if (lane == 0) s_warp[wid] = c;
        __syncthreads();
        if (tid == 0) {
            int t2 = 0;
            for (int w = 0; w < 8; w++) t2 += s_warp[w];
            s_tot = t2;
        }
        __syncthreads();
        return s_tot;
    };

    auto blockScanExcl = [&](int x) -> int {
        __syncthreads();
        int incl = x;
        for (int o = 1; o < 32; o <<= 1) {
            int t2 = __shfl_up_sync(0xffffffffu, incl, o);
            if (lane >= o) incl += t2;
        }
        if (lane == 31) s_warp[wid] = incl;
        __syncthreads();
        if (tid < 8) {
            int t2 = s_warp[tid];
            int inc2 = t2;
            for (int o = 1; o < 8; o <<= 1) {
                int u = __shfl_up_sync(0x000000ffu, inc2, o);
                if (tid >= o) inc2 += u;
            }
            s_warp[tid] = inc2 - t2;
        }
        __syncthreads();
        return s_warp[wid] + incl - x;
    };

    unsigned lo = 0, hi = 0x3F800000u;
    while (lo < hi) {
        unsigned mid = lo + ((hi - lo + 1) >> 1);
        int c = blockCount(mid, false);
        if (c >= TOPK) lo = mid; else hi = mid - 1;
    }
    unsigned V = lo;
    int G  = blockCount(V, true);
    int En = TOPK - G;

    int cgt = 0;
    for (int i = 0; i < 64; i++) cgt += (mv[i * 256 + tid] > V);
    int slot = blockScanExcl(cgt);
    for (int i = 0; i < 64; i++) {
        unsigned x = mv[i * 256 + tid];
        if (x > V) {
            int idx = i * 256 + tid;
            g_topk_val[b * TOPK + slot] = __uint_as_float(x);
            g_topk_idx[b * TOPK + slot] = idx;
            g_topk_cls[b * TOPK + slot] = g_argcls[b * HW + idx];
            slot++;
        }
    }
    int ceq = 0;
    for (int i = 0; i < 64; i++) ceq += (mv[i * 256 + tid] == V);
    int r = blockScanExcl(ceq);
    for (int i = 0; i < 64; i++) {
        unsigned x = mv[i * 256 + tid];
        if (x == V) {
            if (r < En) {
                int idx = i * 256 + tid;
                int s2 = G + r;
                g_topk_val[b * TOPK + s2] = __uint_as_float(x);
                g_topk_idx[b * TOPK + s2] = idx;
                g_topk_cls[b * TOPK + s2] = g_argcls[b * HW + idx];
            }
            r++;
        }
    }
}

// ---------------------------------------------------------------------------
// Gather + L2-normalize feat at peaks (-> q, == k0) and topk pixels (-> ktop).
// One warp per slot; lane handles channels lane and lane+32.
// Also fuses the pseudo_hm scatter (lane 0 of topk slots writes 0.9).
__global__ void gather_kernel(const float* __restrict__ feat, float* __restrict__ out) {
    int gw   = (blockIdx.x * blockDim.x + threadIdx.x) >> 5;
    int lane = threadIdx.x & 31;
    if (gw >= BS * NKEY) return;
    int b = gw / NKEY, s = gw % NKEY;
    float* dst;
    int p;
    if (s < NC) {
        p   = g_peak[b * NC + s];
        dst = g_q + (b * NC + s) * C;
        if (p < 0) { dst[lane] = 0.f; dst[lane + 32] = 0.f; return; }
    } else {
        int j = s - NC;
        p   = g_topk_idx[b * TOPK + j];
        dst = g_ktop + (b * TOPK + j) * C;
        if (lane == 0 && g_topk_val[b * TOPK + j] > 0.f) {
            out[1 + ((size_t)(b * NC + g_topk_cls[b * TOPK + j])) * HW + p] = 0.9f;
        }
    }
    const float* fp = feat + (size_t)b * C * HW + p;
    float a  = fp[(size_t)lane * HW];
    float b2 = fp[(size_t)(lane + 32) * HW];
    float ss = a * a + b2 * b2;
#pragma unroll
    for (int o = 16; o; o >>= 1) ss += __shfl_xor_sync(0xffffffffu, ss, o);
    float inv = 1.f / fmaxf(sqrtf(ss), 1e-12f);
    dst[lane]      = a  * inv;
    dst[lane + 32] = b2 * inv;
}

// ---------------------------------------------------------------------------
// Contrastive loss + final reduction (fused). Block = (batch, 8-class group).
// Each block atomically accumulates its (sum, count); the LAST block to
// finish writes out[0]. FP atomic order variation << 1e-3 tolerance.
__global__ void loss_kernel(float* __restrict__ out) {
    __shared__ float ks[TOPK * C];      // 32 KB (reused for both chunks)
    __shared__ float qs[8 * C];         // 2 KB
    __shared__ float r_s[8], r_d[8], r_n[8];
    __shared__ float acc_s[8], acc_d[8], acc_n[8];
    __shared__ float s_ls, s_lc;
    int b   = blockIdx.x / 10;
    int ng  = blockIdx.x % 10;          // classes [ng*8, ng*8+8)
    int tid = threadIdx.x, lane = tid & 31, wid = tid >> 5;

    if (tid == 0) { s_ls = 0.f; s_lc = 0.f; }

    const float* qb = g_q + b * NC * C;
    for (int i = tid; i < 8 * C; i += 256) qs[i] = qb[ng * 8 * C + i];

    // ---- chunk A: 128 topk keys ----
    const float* kt = g_ktop + b * TOPK * C;
    for (int i = tid; i < TOPK * C; i += 256) ks[i] = kt[i];
    float mallA = 0.f, kvalA = 0.f; int kclsA = -1;
    if (tid < TOPK) {
        kvalA = g_topk_val[b * TOPK + tid];
        mallA = (kvalA > 0.f) ? 1.f : 0.f;
        kclsA = g_topk_cls[b * TOPK + tid];
    }
    __syncthreads();
    for (int nl = 0; nl < 8; nl++) {
        int n = ng * 8 + nl;
        float ssum = 0.f, dsum = 0.f, num = 0.f;
        if (tid < TOPK) {
            float d = 0.f;
            const float* kr = ks + tid * C;
            const float* qr = qs + nl * C;
#pragma unroll
            for (int c = 0; c < C; c++) {
                int cc = (c + tid) & (C - 1);
                d += kr[cc] * qr[cc];
            }
            float dt = d / 0.07f;
            float mm = (kclsA == n && kvalA > 0.f) ? 1.f : 0.f;
            ssum = expf(dt) * mallA;
            dsum = dt * mm;
            num  = mm;
        }
        for (int o = 16; o; o >>= 1) {
            ssum += __shfl_xor_sync(0xffffffffu, ssum, o);
            dsum += __shfl_xor_sync(0xffffffffu, dsum, o);
            num  += __shfl_xor_sync(0xffffffffu, num,  o);
        }
        if (lane == 0) { r_s[wid] = ssum; r_d[wid] = dsum; r_n[wid] = num; }
        __syncthreads();
        if (tid == 0) {
            float S = 0.f, D = 0.f, N = 0.f;
            for (int w = 0; w < 8; w++) { S += r_s[w]; D += r_d[w]; N += r_n[w]; }
            acc_s[nl] = S; acc_d[nl] = D; acc_n[nl] = N;
        }
        __syncthreads();
    }

    // ---- chunk B: 80 k0 keys (== q rows) ----
    for (int i = tid; i < NC * C; i += 256) ks[i] = qb[i];
    float mallB = 0.f;
    if (tid < NC) mallB = g_cmask[b * NC + tid];
    __syncthreads();
    for (int nl = 0; nl < 8; nl++) {
        int n = ng * 8 + nl;
        float cm = g_cmask[b * NC + n];
        float ssum = 0.f, dsum = 0.f, num = 0.f;
        if (tid < NC) {
            float d = 0.f;
            const float* kr = ks + tid * C;
            const float* qr = qs + nl * C;
#pragma unroll
            for (int c = 0; c < C; c++) {
                int cc = (c + tid) & (C - 1);
                d += kr[cc] * qr[cc];
            }
            float dt = d / 0.07f;
            float mm = (tid == n) ? cm : 0.f;   // k0_mask diagonal
            ssum = expf(dt) * mallB;
            dsum = dt * mm;
            num  = mm;
        }
        for (int o = 16; o; o >>= 1) {
            ssum += __shfl_xor_sync(0xffffffffu, ssum, o);
            dsum += __shfl_xor_sync(0xffffffffu, dsum, o);
            num  += __shfl_xor_sync(0xffffffffu, num,  o);
        }
        if (lane == 0) { r_s[wid] = ssum; r_d[wid] = dsum; r_n[wid] = num; }
        __syncthreads();
        if (tid == 0) {
            float S = acc_s[nl], D = acc_d[nl], N = acc_n[nl];
            for (int w = 0; w < 8; w++) { S += r_s[w]; D += r_d[w]; N += r_n[w]; }
            if (cm != 0.f) {
                s_ls += (D - N * logf(S)) / N;  // N >= 1 (diagonal)
                s_lc += cm;
            }
        }
        __syncthreads();
    }

    if (tid == 0) {
        atomicAdd(&g_loss_sum, s_ls);
        atomicAdd(&g_loss_cnt, s_lc);
        __threadfence();
        int done = atomicAdd(&g_loss_done, 1);
        if (done == BS * 10 - 1) {
            out[0] = -(g_loss_sum / g_loss_cnt);
        }
    }
}

// ---------------------------------------------------------------------------
extern "C" void kernel_launch(void* const* d_in, const int* in_sizes, int n_in,
                              void* d_out, int out_size) {
    const float* feat  = (const float*)d_in[0];
    const float* score = (const float*)d_in[1];
    const float* hm    = (const float*)d_in[2];
    float* out = (float*)d_out;

    // Output layout: [ -loss (1 float), pseudo_hm (16*80*128*128 floats) ]
    init_kernel<<<(BS * NC + 255) / 256, 256>>>();
    hm_kernel<<<BS * (HW / 4) / 256, 256>>>(hm, out, out_size);
    score_kernel<<<BS * 16, 256>>>(score, out, out_size);
    rank_kernel<<<BS * SLICES, 256>>>();
    gather_kernel<<<(BS * NKEY * 32 + 255) / 256, 256>>>(feat, out);
    loss_kernel<<<BS * 10, 256>>>(out);
}